// round 14
// baseline (speedup 1.0000x reference)
#include <cuda_runtime.h>
#include <math.h>
#include <stdint.h>

// ---------------------------------------------------------------------------
// Problem constants
// ---------------------------------------------------------------------------
#define BB 128
#define CC 64
#define TT 500
#define NSIG (BB*CC)          // 8192
#define FEAT 16
#define GC 32
#define HH 4
#define NCLS 2

// xl layout strides (conflict-free LDS)
#define SJ 36
#define SH 2312
#define EST 65

// ---------------------------------------------------------------------------
// Device scratch
// ---------------------------------------------------------------------------
__device__ float g_xl1[NSIG * HH * GC];
__device__ float g_skip[NSIG * GC];
__device__ float g_sv1[NSIG * HH];
__device__ float g_dv1[NSIG * HH];
__device__ float g_h1[NSIG * GC];
__device__ float g_sum1[GC];
__device__ float g_sum2[GC];
__device__ float g_pooled[BB * GC];
__device__ int    g_deg[CC];
__device__ float2 g_edges[CC * EST];

__device__ __forceinline__ float eluf(float v) {
    return v > 0.f ? v : (__expf(v) - 1.f);
}
__device__ __forceinline__ float geluf(float v) {
    return 0.5f * v * (1.f + erff(v * 0.70710678118654752f));
}

// ---- packed f32x2 helpers ----
typedef unsigned long long ull;
__device__ __forceinline__ ull pk2(float lo, float hi) {
    ull r;
    asm("mov.b64 %0, {%1, %2};" : "=l"(r) : "f"(lo), "f"(hi));
    return r;
}
__device__ __forceinline__ void upk2(ull v, float& lo, float& hi) {
    asm("mov.b64 {%0, %1}, %2;" : "=f"(lo), "=f"(hi) : "l"(v));
}
__device__ __forceinline__ ull fma2(ull a, ull b, ull c) {
    ull d;
    asm("fma.rn.f32x2 %0, %1, %2, %3;" : "=l"(d) : "l"(a), "l"(b), "l"(c));
    return d;
}
__device__ __forceinline__ unsigned to_tf32(float v) {
    unsigned u;
    asm("cvt.rna.tf32.f32 %0, %1;" : "=r"(u) : "f"(v));
    return u;
}

// ---------------------------------------------------------------------------
// Kernel 1: fused feature extractor + gat1 front-end.
// One block = one signal/node.  conv1 via TF32 tensor-core MMA (m16n8k8).
// ---------------------------------------------------------------------------
struct ExSmem {
    float sx[544];            // tf32-rounded padded input (physical = t + 12)
    float A[16 * 502];        // conv1 out, halo-1 (physical = t + 1)
    float B[16 * 502];        // dw out, halo-1
    unsigned w32[16 * 32];    // tf32 conv1 weights, K padded 25->32 with zeros
    float bn1s[16], bn1b[16];
    float2 spwp[128];         // pointwise weights paired over out-ch
    float2 bn3ps[8], bn3pb[8];
    float dww[48];
    float sdww[48];
    float bn2s[16], bn2b[16];
    float red[8 * 16];
    float feat[16];
    float xlv[128];
};

extern __shared__ unsigned char smem_raw[];

__global__ __launch_bounds__(256) void extractor_kernel(
    const float* __restrict__ x,
    const float* __restrict__ conv1_w, const float* __restrict__ bn_c1,
    const float* __restrict__ dw_w,    const float* __restrict__ bn_c2,
    const float* __restrict__ sdw_w,   const float* __restrict__ spw_w,
    const float* __restrict__ bn_c3,
    const float* __restrict__ gat1w,   const float* __restrict__ asrc,
    const float* __restrict__ adst,    const float* __restrict__ skipw)
{
    ExSmem* s = reinterpret_cast<ExSmem*>(smem_raw);
    const int tid = threadIdx.x;
    const int n = blockIdx.x;

    // ---- cooperative loads ----
    for (int i = tid; i < 544; i += 256) {
        int t = i - 12;
        float v = (t >= 0 && t < TT) ? x[n * TT + t] : 0.f;
        s->sx[i] = __uint_as_float(to_tf32(v));
    }
    for (int i = tid; i < 512; i += 256) {   // tf32 weights, K-padded
        int c = i >> 5, k = i & 31;
        float w = (k < 25) ? conv1_w[c * 25 + k] : 0.f;
        s->w32[i] = to_tf32(w);
    }
    if (tid < 128) {   // paired pointwise: spwp[c*8+op] = (w[2op][c], w[2op+1][c])
        int c = tid >> 3, op = tid & 7;
        s->spwp[tid] = make_float2(spw_w[(2 * op) * 16 + c],
                                   spw_w[(2 * op + 1) * 16 + c]);
    }
    if (tid < 48) { s->dww[tid] = dw_w[tid]; s->sdww[tid] = sdw_w[tid]; }
    if (tid >= 208 && tid < 224) {
        int f = tid - 208;
        float g = bn_c2[f], b = bn_c2[16 + f], m = bn_c2[32 + f], v = bn_c2[48 + f];
        float sc = g * rsqrtf(v + 1e-5f);
        s->bn2s[f] = sc; s->bn2b[f] = b - m * sc;
    } else if (tid >= 224 && tid < 240) {
        int c = tid - 224;
        float g = bn_c1[c], b = bn_c1[16 + c], m = bn_c1[32 + c], v = bn_c1[48 + c];
        float sc = g * rsqrtf(v + 1e-5f);
        s->bn1s[c] = sc; s->bn1b[c] = b - m * sc;
    } else if (tid >= 240 && tid < 248) {
        int p = tid - 240;
        float sc0, sh0, sc1, sh1;
        {   int c = 2 * p;
            float g = bn_c3[c], b = bn_c3[16 + c], m = bn_c3[32 + c], v = bn_c3[48 + c];
            sc0 = g * rsqrtf(v + 1e-5f); sh0 = b - m * sc0; }
        {   int c = 2 * p + 1;
            float g = bn_c3[c], b = bn_c3[16 + c], m = bn_c3[32 + c], v = bn_c3[48 + c];
            sc1 = g * rsqrtf(v + 1e-5f); sh1 = b - m * sc1; }
        s->bn3ps[p] = make_float2(sc0, sc1); s->bn3pb[p] = make_float2(sh0, sh1);
    }
    {   // zero halos of A and B
        int q = tid - 144;
        if (q >= 0 && q < 64) {
            int half = q >> 5, r = q & 31;
            int c = r >> 1, side = r & 1;
            float* arr = half ? s->B : s->A;
            arr[c * 502 + side * 501] = 0.f;
        }
    }
    __syncthreads();

    // ---- conv1 (25-tap) + BN + ELU via TF32 MMA ----
    // A[16ch, 500t] = W[16,32] @ Xim2col[32,500]; 63 n8-tiles x 4 k-steps.
    {
        const int wid = tid >> 5, l = tid & 31;
        const int qr = l >> 2;        // l/4 : 0..7
        const int qc = l & 3;         // l%4
        unsigned af0[4], af1[4], af2[4], af3[4];
        #pragma unroll
        for (int ks = 0; ks < 4; ks++) {
            const int kb = ks * 8;
            af0[ks] = s->w32[qr * 32 + kb + qc];
            af1[ks] = s->w32[(qr + 8) * 32 + kb + qc];
            af2[ks] = s->w32[qr * 32 + kb + qc + 4];
            af3[ks] = s->w32[(qr + 8) * 32 + kb + qc + 4];
        }
        const float s0 = s->bn1s[qr],     h0 = s->bn1b[qr];
        const float s1 = s->bn1s[qr + 8], h1 = s->bn1b[qr + 8];
        for (int tile = wid; tile < 63; tile += 8) {
            const int t0 = tile * 8;
            float c0 = 0.f, c1 = 0.f, c2 = 0.f, c3 = 0.f;
            #pragma unroll
            for (int ks = 0; ks < 4; ks++) {
                const int base = t0 + qr + ks * 8 + qc;  // sx[t + k], phys pad 12
                unsigned b0 = __float_as_uint(s->sx[base]);
                unsigned b1 = __float_as_uint(s->sx[base + 4]);
                asm volatile(
                    "mma.sync.aligned.m16n8k8.row.col.f32.tf32.tf32.f32 "
                    "{%0,%1,%2,%3}, {%4,%5,%6,%7}, {%8,%9}, {%0,%1,%2,%3};"
                    : "+f"(c0), "+f"(c1), "+f"(c2), "+f"(c3)
                    : "r"(af0[ks]), "r"(af1[ks]), "r"(af2[ks]), "r"(af3[ks]),
                      "r"(b0), "r"(b1));
            }
            const int t = t0 + 2 * qc;
            if (t < 500) {
                float* Ar0 = &s->A[qr * 502 + 1 + t];
                float* Ar1 = &s->A[(qr + 8) * 502 + 1 + t];
                Ar0[0] = eluf(c0 * s0 + h0);
                Ar0[1] = eluf(c1 * s0 + h0);
                Ar1[0] = eluf(c2 * s1 + h1);
                Ar1[1] = eluf(c3 * s1 + h1);
            }
        }
    }
    __syncthreads();

    const int g = tid & 127;
    const int cb = tid >> 7;

    // ---- depthwise 3-tap + BN + ELU ----
    if (g < 125) {
        const int t0 = g << 2;
        #pragma unroll
        for (int ci = 0; ci < 8; ci++) {
            const int c = cb * 8 + ci;
            const int base = c * 502 + t0;
            float2 a01 = *reinterpret_cast<const float2*>(&s->A[base]);
            float2 a23 = *reinterpret_cast<const float2*>(&s->A[base + 2]);
            float2 a45 = *reinterpret_cast<const float2*>(&s->A[base + 4]);
            float w0 = s->dww[c * 3], w1v = s->dww[c * 3 + 1], w2v = s->dww[c * 3 + 2];
            float sc = s->bn2s[c], sh = s->bn2b[c];
            float* Bp = &s->B[base + 1];
            Bp[0] = eluf((a01.x * w0 + a01.y * w1v + a23.x * w2v) * sc + sh);
            Bp[1] = eluf((a01.y * w0 + a23.x * w1v + a23.y * w2v) * sc + sh);
            Bp[2] = eluf((a23.x * w0 + a23.y * w1v + a45.x * w2v) * sc + sh);
            Bp[3] = eluf((a23.y * w0 + a45.x * w1v + a45.y * w2v) * sc + sh);
        }
    }
    __syncthreads();

    // ---- sdw(3-tap) -> pointwise 16x16 (f32x2) -> BN -> ELU -> sum ----
    float acc[16];
    #pragma unroll
    for (int o = 0; o < 16; o++) acc[o] = 0.f;
    if (tid < 250) {
        const int t0 = tid * 2;
        ull accA[8], accB[8];
        #pragma unroll
        for (int op = 0; op < 8; op++) { accA[op] = 0; accB[op] = 0; }
        const ull* spwu = reinterpret_cast<const ull*>(s->spwp);
        #pragma unroll
        for (int c = 0; c < 16; c++) {
            const int base = c * 502 + t0;
            float2 b01 = *reinterpret_cast<const float2*>(&s->B[base]);
            float2 b23 = *reinterpret_cast<const float2*>(&s->B[base + 2]);
            float w0 = s->sdww[c * 3], w1v = s->sdww[c * 3 + 1], w2v = s->sdww[c * 3 + 2];
            float sd0 = b01.x * w0 + b01.y * w1v + b23.x * w2v;
            float sd1 = b01.y * w0 + b23.x * w1v + b23.y * w2v;
            ull d0 = pk2(sd0, sd0), d1 = pk2(sd1, sd1);
            #pragma unroll
            for (int op = 0; op < 8; op++) {
                ull w = spwu[c * 8 + op];
                accA[op] = fma2(d0, w, accA[op]);
                accB[op] = fma2(d1, w, accB[op]);
            }
        }
        const ull* bs = reinterpret_cast<const ull*>(s->bn3ps);
        const ull* bb = reinterpret_cast<const ull*>(s->bn3pb);
        #pragma unroll
        for (int op = 0; op < 8; op++) {
            ull ya = fma2(accA[op], bs[op], bb[op]);
            ull yb = fma2(accB[op], bs[op], bb[op]);
            float a0, a1, c0, c1;
            upk2(ya, a0, a1); upk2(yb, c0, c1);
            acc[2 * op]     = eluf(a0) + eluf(c0);
            acc[2 * op + 1] = eluf(a1) + eluf(c1);
        }
    }
    int lane = tid & 31, warp = tid >> 5;
    #pragma unroll
    for (int o = 0; o < 16; o++) {
        float v = acc[o];
        #pragma unroll
        for (int off = 16; off > 0; off >>= 1) v += __shfl_xor_sync(0xffffffffu, v, off);
        if (lane == 0) s->red[warp * 16 + o] = v;
    }
    __syncthreads();
    if (tid < 16) {
        float v = 0.f;
        #pragma unroll
        for (int w = 0; w < 8; w++) v += s->red[w * 16 + tid];
        s->feat[tid] = v * (1.f / 500.f);
    }
    __syncthreads();

    // ---- gat1 front-end: xl1 = feat @ W1, skip = feat @ skw^T ----
    if (tid < 128) {
        float a = 0.f;
        #pragma unroll
        for (int d = 0; d < FEAT; d++) a += s->feat[d] * __ldg(&gat1w[d * 128 + tid]);
        s->xlv[tid] = a;
        g_xl1[n * 128 + tid] = a;
    } else if (tid < 160) {
        const int f = tid - 128;
        float a = 0.f;
        #pragma unroll
        for (int d = 0; d < FEAT; d++) a += s->feat[d] * __ldg(&skipw[f * FEAT + d]);
        g_skip[n * GC + f] = a;
    }
    __syncthreads();
    if (tid < 8) {
        const int h = tid >> 1, which = tid & 1;
        const float* av = which ? adst : asrc;
        float a = 0.f;
        #pragma unroll
        for (int f2 = 0; f2 < GC; f2++) a += s->xlv[h * GC + f2] * __ldg(&av[h * GC + f2]);
        if (which) g_dv1[n * HH + h] = a;
        else       g_sv1[n * HH + h] = a;
    }
}

// ---------------------------------------------------------------------------
// Kernel 2: build padded edge rows + zero SE accumulators
// ---------------------------------------------------------------------------
__global__ __launch_bounds__(256) void graph_kernel(
    const float* __restrict__ node_embed, const int* __restrict__ edges)
{
    __shared__ float E[CC * FEAT];
    __shared__ float ee[CC * CC];
    __shared__ float rowsum[CC];
    __shared__ float msm[CC * CC];
    const int tid = threadIdx.x;

    if (tid < GC) { g_sum1[tid] = 0.f; g_sum2[tid] = 0.f; }

    for (int i = tid; i < CC * FEAT; i += 256) E[i] = node_embed[i];
    for (int i = tid; i < CC * CC; i += 256) msm[i] = 0.f;
    __syncthreads();

    for (int idx = tid; idx < CC * CC; idx += 256) {
        int i = idx >> 6, j = idx & 63;
        float v = 0.f;
        #pragma unroll
        for (int d = 0; d < FEAT; d++) v += E[i * FEAT + d] * E[j * FEAT + d];
        ee[idx] = v > 0.f ? v : 0.f;
    }
    __syncthreads();

    if (tid < CC) {
        float v = 0.f;
        #pragma unroll
        for (int j = 0; j < CC; j++) v += ee[tid * CC + j];
        rowsum[tid] = v;
    }
    {
        int e = tid;
        int src = edges[e], dst = edges[256 + e];
        atomicAdd(&msm[src * CC + dst], 1.0f);
    }
    __syncthreads();

    if (tid < CC) {
        const int i = tid;
        const float inv = 1.f / (rowsum[i] + 1e-6f);
        int d = 0;
        for (int j = 0; j < CC; j++) {
            float Mv;
            if (i == j) {
                Mv = 1.f;
            } else {
                float dyn = (ee[i * CC + j] * inv) > 0.1f ? 1.f : 0.f;
                Mv = msm[i * CC + j] + dyn;
            }
            if (Mv > 0.f) {
                g_edges[i * EST + d] = make_float2(__int_as_float(j), __logf(Mv));
                d++;
            }
        }
        g_deg[i] = d;
        for (int k = d; k < EST; k++)
            g_edges[i * EST + k] = make_float2(__int_as_float(i), -1e30f);
    }
}

// ---------------------------------------------------------------------------
// GAT layer 1: attention-only (xl/sv/dv/skip precomputed by extractor)
// ---------------------------------------------------------------------------
struct G1Smem {
    float xl[HH * SH];
    float sv[CC * HH];
    float dv[CC * HH];
    float skip[CC * GC];
    float bns[GC], bnb[GC], bias[GC], bsum[GC];
    float sbuf[256];
    float abuf[256 * 33];
    float2 earr[CC * EST];
    int   sdeg[CC];
};

__global__ __launch_bounds__(512) void gat1_kernel(
    const float* __restrict__ biasg, const float* __restrict__ bng)
{
    G1Smem* s = reinterpret_cast<G1Smem*>(smem_raw);
    const int tid = threadIdx.x;
    const int b = blockIdx.x;

    {
        const float4* src = reinterpret_cast<const float4*>(&g_xl1[b * CC * 128]);
        #pragma unroll
        for (int q = 0; q < 4; q++) {
            int idx4 = tid + q * 512;
            int idx = idx4 * 4;
            int j = idx >> 7, col = idx & 127;
            int h = col >> 5, f = col & 31;
            float4 v = src[idx4];
            *reinterpret_cast<float4*>(&s->xl[h * SH + j * SJ + f]) = v;
        }
    }
    if (tid < 256) {
        s->sv[tid] = g_sv1[b * 256 + tid];
        s->dv[tid] = g_dv1[b * 256 + tid];
    }
    {
        const float4* src = reinterpret_cast<const float4*>(&g_skip[b * CC * GC]);
        float4 v = src[tid];
        *reinterpret_cast<float4*>(&s->skip[tid * 4]) = v;
    }
    for (int i = tid; i < CC * EST; i += 512) s->earr[i] = g_edges[i];
    if (tid < CC) s->sdeg[tid] = g_deg[tid];
    if (tid < GC) {
        float g = bng[tid], bb2 = bng[GC + tid], m = bng[2 * GC + tid], v = bng[3 * GC + tid];
        float sc = g * rsqrtf(v + 1e-5f);
        s->bns[tid] = sc; s->bnb[tid] = bb2 - m * sc;
        s->bias[tid] = biasg[tid];
        s->bsum[tid] = 0.f;
    }
    __syncthreads();

    const int r = tid & 255;
    const int half = tid >> 8;
    const int i = r >> 2, h = r & 3;
    const float di = s->dv[i * HH + h];
    const int deg = s->sdeg[i];
    const float2* erow = &s->earr[i * EST];

    float mx = -1e30f;
    for (int k = 0; k < deg; k++) {
        float2 e = erow[k];
        int j = __float_as_int(e.x);
        float l = di + s->sv[j * HH + h];
        l = l > 0.f ? l : 0.2f * l;
        l += e.y;
        mx = fmaxf(mx, l);
    }
    float acc[GC];
    #pragma unroll
    for (int f = 0; f < GC; f++) acc[f] = 0.f;
    float ssum = 0.f;
    for (int k = half; k < deg; k += 2) {
        float2 e = erow[k];
        int j = __float_as_int(e.x);
        float l = di + s->sv[j * HH + h];
        l = l > 0.f ? l : 0.2f * l;
        l += e.y;
        float w = __expf(l - mx);
        ssum += w;
        const float4* xp4 = reinterpret_cast<const float4*>(&s->xl[h * SH + j * SJ]);
        #pragma unroll
        for (int m = 0; m < 8; m++) {
            float4 v = xp4[m];
            acc[m * 4 + 0] += w * v.x; acc[m * 4 + 1] += w * v.y;
            acc[m * 4 + 2] += w * v.z; acc[m * 4 + 3] += w * v.w;
        }
    }
    if (half == 1) {
        #pragma unroll
        for (int f = 0; f < GC; f++) s->abuf[r * 33 + f] = acc[f];
        s->sbuf[r] = ssum;
    }
    __syncthreads();
    if (half == 0) {
        ssum += s->sbuf[r];
        #pragma unroll
        for (int f = 0; f < GC; f++) acc[f] += s->abuf[r * 33 + f];
        const float inv = 1.f / ssum;
        #pragma unroll
        for (int f = 0; f < GC; f++) {
            float v = acc[f] * inv;
            v += __shfl_xor_sync(0xffffffffu, v, 1);
            v += __shfl_xor_sync(0xffffffffu, v, 2);
            acc[f] = v * 0.25f;
        }
        if (h == 0) {
            float vals[GC];
            #pragma unroll
            for (int f = 0; f < GC; f++) {
                float o = acc[f] + s->bias[f];
                o = o * s->bns[f] + s->bnb[f];
                float val = geluf(o + s->skip[i * GC + f]);
                g_h1[(b * CC + i) * GC + f] = val;
                vals[f] = val;
            }
            #pragma unroll
            for (int f = 0; f < GC; f++) {
                float v = vals[f];
                v += __shfl_xor_sync(0x11111111u, v, 4);
                v += __shfl_xor_sync(0x11111111u, v, 8);
                v += __shfl_xor_sync(0x11111111u, v, 16);
                if ((tid & 31) == 0) atomicAdd(&s->bsum[f], v);
            }
        }
    }
    __syncthreads();
    if (tid < GC) atomicAdd(&g_sum1[tid], s->bsum[tid]);
}

// ---------------------------------------------------------------------------
// GAT layer 2 (SE1 gate applied inline), ILP-4 GEMM with register weights
// ---------------------------------------------------------------------------
struct G2Smem {
    float xin[CC * GC];
    float W[GC * HH * GC];
    float xl[HH * SH];
    float sv[CC * HH];
    float dv[CC * HH];
    float as[HH * GC];
    float ad[HH * GC];
    float bns[GC], bnb[GC], bias[GC], bsum[GC];
    float sew1[8 * GC];
    float sew2[GC * 8];
    float gate[GC];
    float hid[8];
    float sbuf[256];
    float abuf[256 * 33];
    float2 earr[CC * EST];
    int   sdeg[CC];
};

__global__ __launch_bounds__(512) void gat2_kernel(
    const float* __restrict__ Wg, const float* __restrict__ asrc,
    const float* __restrict__ adst, const float* __restrict__ biasg,
    const float* __restrict__ bng,
    const float* __restrict__ se1w1, const float* __restrict__ se1w2)
{
    G2Smem* s = reinterpret_cast<G2Smem*>(smem_raw);
    const int tid = threadIdx.x;
    const int b = blockIdx.x;

    for (int i = tid; i < CC * GC; i += 512) s->xin[i] = g_h1[b * CC * GC + i];
    for (int i = tid; i < 4096; i += 512) s->W[i] = Wg[i];
    for (int i = tid; i < CC * EST; i += 512) s->earr[i] = g_edges[i];
    if (tid < CC) s->sdeg[tid] = g_deg[tid];
    if (tid < 128) { s->as[tid] = asrc[tid]; s->ad[tid] = adst[tid]; }
    if (tid < 256) { s->sew1[tid] = se1w1[tid]; s->sew2[tid] = se1w2[tid]; }
    if (tid < GC) {
        float g = bng[tid], bb2 = bng[GC + tid], m = bng[2 * GC + tid], v = bng[3 * GC + tid];
        float sc = g * rsqrtf(v + 1e-5f);
        s->bns[tid] = sc; s->bnb[tid] = bb2 - m * sc;
        s->bias[tid] = biasg[tid];
        s->bsum[tid] = 0.f;
    }
    __syncthreads();

    if (tid < 8) {
        float a = 0.f;
        #pragma unroll
        for (int f = 0; f < GC; f++) a += (g_sum1[f] * (1.f / (float)NSIG)) * s->sew1[tid * GC + f];
        s->hid[tid] = a > 0.f ? a : 0.f;
    }
    __syncthreads();
    if (tid < GC) {
        float a = 0.f;
        #pragma unroll
        for (int k = 0; k < 8; k++) a += s->hid[k] * s->sew2[tid * 8 + k];
        s->gate[tid] = 1.f / (1.f + __expf(-a));
    }
    __syncthreads();
    for (int idx = tid; idx < CC * GC; idx += 512) s->xin[idx] *= s->gate[idx & 31];
    __syncthreads();

    {
        const int col = tid & 127;
        const int jg = tid >> 7;
        const int h = col >> 5, f = col & 31;
        float wreg[GC];
        #pragma unroll
        for (int d = 0; d < GC; d++) wreg[d] = s->W[d * 128 + col];
        #pragma unroll
        for (int q = 0; q < 4; q++) {
            const int j0 = jg * 16 + q * 4;
            float a0 = 0.f, a1 = 0.f, a2 = 0.f, a3 = 0.f;
            #pragma unroll
            for (int dc = 0; dc < 8; dc++) {
                const float4 x0 = *reinterpret_cast<const float4*>(&s->xin[(j0 + 0) * GC + dc * 4]);
                const float4 x1 = *reinterpret_cast<const float4*>(&s->xin[(j0 + 1) * GC + dc * 4]);
                const float4 x2 = *reinterpret_cast<const float4*>(&s->xin[(j0 + 2) * GC + dc * 4]);
                const float4 x3 = *reinterpret_cast<const float4*>(&s->xin[(j0 + 3) * GC + dc * 4]);
                const float w0 = wreg[dc * 4], w1 = wreg[dc * 4 + 1];
                const float w2 = wreg[dc * 4 + 2], w3 = wreg[dc * 4 + 3];
                a0 += x0.x * w0 + x0.y * w1 + x0.z * w2 + x0.w * w3;
                a1 += x1.x * w0 + x1.y * w1 + x1.z * w2 + x1.w * w3;
                a2 += x2.x * w0 + x2.y * w1 + x2.z * w2 + x2.w * w3;
                a3 += x3.x * w0 + x3.y * w1 + x3.z * w2 + x3.w * w3;
            }
            s->xl[h * SH + (j0 + 0) * SJ + f] = a0;
            s->xl[h * SH + (j0 + 1) * SJ + f] = a1;
            s->xl[h * SH + (j0 + 2) * SJ + f] = a2;
            s->xl[h * SH + (j0 + 3) * SJ + f] = a3;
        }
    }
    __syncthreads();

    if (tid < 256) {
        int j = tid >> 2, h = tid & 3;
        const float4* xp4 = reinterpret_cast<const float4*>(&s->xl[h * SH + j * SJ]);
        const float4* as4 = reinterpret_cast<const float4*>(&s->as[h * GC]);
        const float4* ad4 = reinterpret_cast<const float4*>(&s->ad[h * GC]);
        float sa = 0.f, da = 0.f;
        #pragma unroll
        for (int m = 0; m < 8; m++) {
            float4 xv = xp4[m], av = as4[m], dvv = ad4[m];
            sa += xv.x * av.x + xv.y * av.y + xv.z * av.z + xv.w * av.w;
            da += xv.x * dvv.x + xv.y * dvv.y + xv.z * dvv.z + xv.w * dvv.w;
        }
        s->sv[j * HH + h] = sa;
        s->dv[j * HH + h] = da;
    }
    __syncthreads();

    const int r = tid & 255;
    const int half = tid >> 8;
    const int i = r >> 2, h = r & 3;
    const float di = s->dv[i * HH + h];
    const int deg = s->sdeg[i];
    const float2* erow = &s->earr[i * EST];

    float mx = -1e30f;
    for (int k = 0; k < deg; k++) {
        float2 e = erow[k];
        int j = __float_as_int(e.x);
        float l = di + s->sv[j * HH + h];
        l = l > 0.f ? l : 0.2f * l;
        l += e.y;
        mx = fmaxf(mx, l);
    }
    float acc[GC];
    #pragma unroll
    for (int f = 0; f < GC; f++) acc[f] = 0.f;
    float ssum = 0.f;
    for (int k = half; k < deg; k += 2) {
        float2 e = erow[k];
        int j = __float_as_int(e.x);
        float l = di + s->sv[j * HH + h];
        l = l > 0.f ? l : 0.2f * l;
        l += e.y;
        float w = __expf(l - mx);
        ssum += w;
        const float4* xp4 = reinterpret_cast<const float4*>(&s->xl[h * SH + j * SJ]);
        #pragma unroll
        for (int m = 0; m < 8; m++) {
            float4 v = xp4[m];
            acc[m * 4 + 0] += w * v.x; acc[m * 4 + 1] += w * v.y;
            acc[m * 4 + 2] += w * v.z; acc[m * 4 + 3] += w * v.w;
        }
    }
    if (half == 1) {
        #pragma unroll
        for (int f = 0; f < GC; f++) s->abuf[r * 33 + f] = acc[f];
        s->sbuf[r] = ssum;
    }
    __syncthreads();
    if (half == 0) {
        ssum += s->sbuf[r];
        #pragma unroll
        for (int f = 0; f < GC; f++) acc[f] += s->abuf[r * 33 + f];
        const float inv = 1.f / ssum;
        #pragma unroll
        for (int f = 0; f < GC; f++) {
            float v = acc[f] * inv;
            v += __shfl_xor_sync(0xffffffffu, v, 1);
            v += __shfl_xor_sync(0xffffffffu, v, 2);
            acc[f] = v * 0.25f;
        }
        if (h == 0) {
            float vals[GC];
            #pragma unroll
            for (int f = 0; f < GC; f++) {
                float o = acc[f] + s->bias[f];
                o = o * s->bns[f] + s->bnb[f];
                vals[f] = geluf(o + s->xin[i * GC + f]);
            }
            #pragma unroll
            for (int f = 0; f < GC; f++) {
                float v = vals[f];
                v += __shfl_xor_sync(0x11111111u, v, 4);
                v += __shfl_xor_sync(0x11111111u, v, 8);
                v += __shfl_xor_sync(0x11111111u, v, 16);
                if ((tid & 31) == 0) atomicAdd(&s->bsum[f], v);
            }
        }
    }
    __syncthreads();
    if (tid < GC) {
        atomicAdd(&g_sum2[tid], s->bsum[tid]);
        g_pooled[b * GC + tid] = s->bsum[tid] * (1.f / (float)CC);
    }
}

// ---------------------------------------------------------------------------
// Final: SE2 gate + classifier
// ---------------------------------------------------------------------------
__global__ __launch_bounds__(256) void final_kernel(
    const float* __restrict__ se2w1, const float* __restrict__ se2w2,
    const float* __restrict__ clfw, const float* __restrict__ clfb,
    float* __restrict__ out)
{
    __shared__ float hid[8];
    __shared__ float gate[GC];
    const int tid = threadIdx.x;
    if (tid < 8) {
        float a = 0.f;
        #pragma unroll
        for (int f = 0; f < GC; f++) a += (g_sum2[f] * (1.f / (float)NSIG)) * se2w1[tid * GC + f];
        hid[tid] = a > 0.f ? a : 0.f;
    }
    __syncthreads();
    if (tid < GC) {
        float a = 0.f;
        #pragma unroll
        for (int k = 0; k < 8; k++) a += hid[k] * se2w2[tid * 8 + k];
        gate[tid] = 1.f / (1.f + __expf(-a));
    }
    __syncthreads();
    {
        int b = tid >> 1, n = tid & 1;
        float a = clfb[n];
        #pragma unroll
        for (int f = 0; f < GC; f++)
            a += g_pooled[b * GC + f] * gate[f] * clfw[n * GC + f];
        out[b * NCLS + n] = a;
    }
}

// ---------------------------------------------------------------------------
// kernel_launch
// ---------------------------------------------------------------------------
extern "C" void kernel_launch(void* const* d_in, const int* in_sizes, int n_in,
                              void* d_out, int out_size)
{
    const float* x         = (const float*)d_in[0];
    const int*   edges     = (const int*)  d_in[1];
    const float* conv1_w   = (const float*)d_in[2];
    const float* bn_c1     = (const float*)d_in[3];
    const float* dw_w      = (const float*)d_in[4];
    const float* bn_c2     = (const float*)d_in[5];
    const float* sdw_w     = (const float*)d_in[6];
    const float* spw_w     = (const float*)d_in[7];
    const float* bn_c3     = (const float*)d_in[8];
    const float* node_emb  = (const float*)d_in[9];
    const float* gat1_w    = (const float*)d_in[10];
    const float* gat1_as   = (const float*)d_in[11];
    const float* gat1_ad   = (const float*)d_in[12];
    const float* gat1_b    = (const float*)d_in[13];
    const float* bn_g1     = (const float*)d_in[14];
    const float* skip1_w   = (const float*)d_in[15];
    const float* se1_w1    = (const float*)d_in[16];
    const float* se1_w2    = (const float*)d_in[17];
    const float* gat2_w    = (const float*)d_in[18];
    const float* gat2_as   = (const float*)d_in[19];
    const float* gat2_ad   = (const float*)d_in[20];
    const float* gat2_b    = (const float*)d_in[21];
    const float* bn_g2     = (const float*)d_in[22];
    const float* se2_w1    = (const float*)d_in[23];
    const float* se2_w2    = (const float*)d_in[24];
    const float* clf_w     = (const float*)d_in[25];
    const float* clf_b     = (const float*)d_in[26];
    float* out = (float*)d_out;

    cudaFuncSetAttribute(extractor_kernel, cudaFuncAttributeMaxDynamicSharedMemorySize, (int)sizeof(ExSmem));
    cudaFuncSetAttribute(gat1_kernel,      cudaFuncAttributeMaxDynamicSharedMemorySize, (int)sizeof(G1Smem));
    cudaFuncSetAttribute(gat2_kernel,      cudaFuncAttributeMaxDynamicSharedMemorySize, (int)sizeof(G2Smem));

    extractor_kernel<<<NSIG, 256, sizeof(ExSmem)>>>(x, conv1_w, bn_c1, dw_w, bn_c2,
                                                    sdw_w, spw_w, bn_c3,
                                                    gat1_w, gat1_as, gat1_ad, skip1_w);
    graph_kernel<<<1, 256>>>(node_emb, edges);
    gat1_kernel<<<BB, 512, sizeof(G1Smem)>>>(gat1_b, bn_g1);
    gat2_kernel<<<BB, 512, sizeof(G2Smem)>>>(gat2_w, gat2_as, gat2_ad, gat2_b, bn_g2, se1_w1, se1_w2);
    final_kernel<<<1, 256>>>(se2_w1, se2_w2, clf_w, clf_b, out);
}

// round 15
// speedup vs baseline: 1.0229x; 1.0229x over previous
#include <cuda_runtime.h>
#include <math.h>
#include <stdint.h>

// ---------------------------------------------------------------------------
// Problem constants
// ---------------------------------------------------------------------------
#define BB 128
#define CC 64
#define TT 500
#define NSIG (BB*CC)          // 8192
#define FEAT 16
#define GC 32
#define HH 4
#define NCLS 2

// xl layout strides (conflict-free LDS)
#define SJ 36
#define SH 2312
#define EST 65
// A row stride: 516 mod 32 == 4  -> <=2-way STS conflicts in conv1 epilogue
#define AST 516

// ---------------------------------------------------------------------------
// Device scratch
// ---------------------------------------------------------------------------
__device__ float g_xl1[NSIG * HH * GC];
__device__ float g_skip[NSIG * GC];
__device__ float g_sv1[NSIG * HH];
__device__ float g_dv1[NSIG * HH];
__device__ float g_h1[NSIG * GC];
__device__ float g_sum1[GC];
__device__ float g_sum2[GC];
__device__ float g_pooled[BB * GC];
__device__ int    g_deg[CC];
__device__ float2 g_edges[CC * EST];

__device__ __forceinline__ float eluf(float v) {
    return v > 0.f ? v : (__expf(v) - 1.f);
}
__device__ __forceinline__ float geluf(float v) {
    return 0.5f * v * (1.f + erff(v * 0.70710678118654752f));
}

// ---- packed f32x2 helpers ----
typedef unsigned long long ull;
__device__ __forceinline__ ull pk2(float lo, float hi) {
    ull r;
    asm("mov.b64 %0, {%1, %2};" : "=l"(r) : "f"(lo), "f"(hi));
    return r;
}
__device__ __forceinline__ void upk2(ull v, float& lo, float& hi) {
    asm("mov.b64 {%0, %1}, %2;" : "=f"(lo), "=f"(hi) : "l"(v));
}
__device__ __forceinline__ ull fma2(ull a, ull b, ull c) {
    ull d;
    asm("fma.rn.f32x2 %0, %1, %2, %3;" : "=l"(d) : "l"(a), "l"(b), "l"(c));
    return d;
}
__device__ __forceinline__ unsigned to_tf32(float v) {
    unsigned u;
    asm("cvt.rna.tf32.f32 %0, %1;" : "=r"(u) : "f"(v));
    return u;
}
__device__ __forceinline__ void mma_tf32(
    float& c0, float& c1, float& c2, float& c3,
    unsigned a0, unsigned a1, unsigned a2, unsigned a3,
    unsigned b0, unsigned b1)
{
    asm volatile(
        "mma.sync.aligned.m16n8k8.row.col.f32.tf32.tf32.f32 "
        "{%0,%1,%2,%3}, {%4,%5,%6,%7}, {%8,%9}, {%0,%1,%2,%3};"
        : "+f"(c0), "+f"(c1), "+f"(c2), "+f"(c3)
        : "r"(a0), "r"(a1), "r"(a2), "r"(a3), "r"(b0), "r"(b1));
}

// ---------------------------------------------------------------------------
// Kernel 1: fused feature extractor + gat1 front-end.
// One block = one signal/node.  conv1 via TF32 MMA, 2-tile interleave.
// ---------------------------------------------------------------------------
struct ExSmem {
    float sx[544];            // tf32-rounded padded input (physical = t + 12)
    float A[16 * AST];        // conv1 out, halo-1 (physical = t + 1), stride 516
    float B[16 * 502];        // dw out, halo-1, stride 502
    unsigned w32[16 * 32];    // tf32 conv1 weights, K padded 25->32 with zeros
    float bn1s[16], bn1b[16];
    float2 spwp[128];         // pointwise weights paired over out-ch
    float2 bn3ps[8], bn3pb[8];
    float dww[48];
    float sdww[48];
    float bn2s[16], bn2b[16];
    float red[8 * 16];
    float feat[16];
    float xlv[128];
};

extern __shared__ unsigned char smem_raw[];

__global__ __launch_bounds__(256) void extractor_kernel(
    const float* __restrict__ x,
    const float* __restrict__ conv1_w, const float* __restrict__ bn_c1,
    const float* __restrict__ dw_w,    const float* __restrict__ bn_c2,
    const float* __restrict__ sdw_w,   const float* __restrict__ spw_w,
    const float* __restrict__ bn_c3,
    const float* __restrict__ gat1w,   const float* __restrict__ asrc,
    const float* __restrict__ adst,    const float* __restrict__ skipw)
{
    ExSmem* s = reinterpret_cast<ExSmem*>(smem_raw);
    const int tid = threadIdx.x;
    const int n = blockIdx.x;

    // ---- cooperative loads ----
    for (int i = tid; i < 544; i += 256) {
        int t = i - 12;
        float v = (t >= 0 && t < TT) ? x[n * TT + t] : 0.f;
        s->sx[i] = __uint_as_float(to_tf32(v));
    }
    for (int i = tid; i < 512; i += 256) {   // tf32 weights, K-padded
        int c = i >> 5, k = i & 31;
        float w = (k < 25) ? conv1_w[c * 25 + k] : 0.f;
        s->w32[i] = to_tf32(w);
    }
    if (tid < 128) {   // paired pointwise: spwp[c*8+op] = (w[2op][c], w[2op+1][c])
        int c = tid >> 3, op = tid & 7;
        s->spwp[tid] = make_float2(spw_w[(2 * op) * 16 + c],
                                   spw_w[(2 * op + 1) * 16 + c]);
    }
    if (tid < 48) { s->dww[tid] = dw_w[tid]; s->sdww[tid] = sdw_w[tid]; }
    if (tid >= 208 && tid < 224) {
        int f = tid - 208;
        float g = bn_c2[f], b = bn_c2[16 + f], m = bn_c2[32 + f], v = bn_c2[48 + f];
        float sc = g * rsqrtf(v + 1e-5f);
        s->bn2s[f] = sc; s->bn2b[f] = b - m * sc;
    } else if (tid >= 224 && tid < 240) {
        int c = tid - 224;
        float g = bn_c1[c], b = bn_c1[16 + c], m = bn_c1[32 + c], v = bn_c1[48 + c];
        float sc = g * rsqrtf(v + 1e-5f);
        s->bn1s[c] = sc; s->bn1b[c] = b - m * sc;
    } else if (tid >= 240 && tid < 248) {
        int p = tid - 240;
        float sc0, sh0, sc1, sh1;
        {   int c = 2 * p;
            float g = bn_c3[c], b = bn_c3[16 + c], m = bn_c3[32 + c], v = bn_c3[48 + c];
            sc0 = g * rsqrtf(v + 1e-5f); sh0 = b - m * sc0; }
        {   int c = 2 * p + 1;
            float g = bn_c3[c], b = bn_c3[16 + c], m = bn_c3[32 + c], v = bn_c3[48 + c];
            sc1 = g * rsqrtf(v + 1e-5f); sh1 = b - m * sc1; }
        s->bn3ps[p] = make_float2(sc0, sc1); s->bn3pb[p] = make_float2(sh0, sh1);
    }
    {   // zero halos of A (stride 516) and B (stride 502)
        int q = tid - 144;
        if (q >= 0 && q < 64) {
            int half = q >> 5, r = q & 31;
            int c = r >> 1, side = r & 1;
            if (half) s->B[c * 502 + side * 501] = 0.f;
            else      s->A[c * AST + side * 501] = 0.f;
        }
    }
    __syncthreads();

    // ---- conv1 (25-tap) + BN + ELU via TF32 MMA, 2-tile interleave ----
    // A[16ch, 500t] = W[16,32] @ Xim2col[32,512]; 64 n8-tiles, 8 per warp.
    {
        const int wid = tid >> 5, l = tid & 31;
        const int qr = l >> 2;        // 0..7
        const int qc = l & 3;         // 0..3
        unsigned af0[4], af1[4], af2[4], af3[4];
        #pragma unroll
        for (int ks = 0; ks < 4; ks++) {
            const int kb = ks * 8;
            af0[ks] = s->w32[qr * 32 + kb + qc];
            af1[ks] = s->w32[(qr + 8) * 32 + kb + qc];
            af2[ks] = s->w32[qr * 32 + kb + qc + 4];
            af3[ks] = s->w32[(qr + 8) * 32 + kb + qc + 4];
        }
        const float s0 = s->bn1s[qr],     h0 = s->bn1b[qr];
        const float s1 = s->bn1s[qr + 8], h1 = s->bn1b[qr + 8];
        #pragma unroll
        for (int q = 0; q < 4; q++) {
            const int t0a = (wid * 8 + 2 * q) * 8;
            const int t0b = t0a + 8;
            float a0 = 0.f, a1 = 0.f, a2 = 0.f, a3 = 0.f;
            float b0 = 0.f, b1 = 0.f, b2 = 0.f, b3 = 0.f;
            #pragma unroll
            for (int ks = 0; ks < 4; ks++) {
                const int ba = t0a + qr + ks * 8 + qc;
                unsigned xa0 = __float_as_uint(s->sx[ba]);
                unsigned xa1 = __float_as_uint(s->sx[ba + 4]);
                unsigned xb0 = __float_as_uint(s->sx[ba + 8]);
                unsigned xb1 = __float_as_uint(s->sx[ba + 12]);
                mma_tf32(a0, a1, a2, a3, af0[ks], af1[ks], af2[ks], af3[ks], xa0, xa1);
                mma_tf32(b0, b1, b2, b3, af0[ks], af1[ks], af2[ks], af3[ks], xb0, xb1);
            }
            {   // epilogue tile A
                const int t = t0a + 2 * qc;
                if (t < 500) {
                    float* r0 = &s->A[qr * AST + 1 + t];
                    float* r1 = &s->A[(qr + 8) * AST + 1 + t];
                    r0[0] = eluf(a0 * s0 + h0);
                    r0[1] = eluf(a1 * s0 + h0);
                    r1[0] = eluf(a2 * s1 + h1);
                    r1[1] = eluf(a3 * s1 + h1);
                }
            }
            {   // epilogue tile B
                const int t = t0b + 2 * qc;
                if (t < 500) {
                    float* r0 = &s->A[qr * AST + 1 + t];
                    float* r1 = &s->A[(qr + 8) * AST + 1 + t];
                    r0[0] = eluf(b0 * s0 + h0);
                    r0[1] = eluf(b1 * s0 + h0);
                    r1[0] = eluf(b2 * s1 + h1);
                    r1[1] = eluf(b3 * s1 + h1);
                }
            }
        }
    }
    __syncthreads();

    const int g = tid & 127;
    const int cb = tid >> 7;

    // ---- depthwise 3-tap + BN + ELU ----
    if (g < 125) {
        const int t0 = g << 2;
        #pragma unroll
        for (int ci = 0; ci < 8; ci++) {
            const int c = cb * 8 + ci;
            const int base = c * AST + t0;
            float2 a01 = *reinterpret_cast<const float2*>(&s->A[base]);
            float2 a23 = *reinterpret_cast<const float2*>(&s->A[base + 2]);
            float2 a45 = *reinterpret_cast<const float2*>(&s->A[base + 4]);
            float w0 = s->dww[c * 3], w1v = s->dww[c * 3 + 1], w2v = s->dww[c * 3 + 2];
            float sc = s->bn2s[c], sh = s->bn2b[c];
            float* Bp = &s->B[c * 502 + t0 + 1];
            Bp[0] = eluf((a01.x * w0 + a01.y * w1v + a23.x * w2v) * sc + sh);
            Bp[1] = eluf((a01.y * w0 + a23.x * w1v + a23.y * w2v) * sc + sh);
            Bp[2] = eluf((a23.x * w0 + a23.y * w1v + a45.x * w2v) * sc + sh);
            Bp[3] = eluf((a23.y * w0 + a45.x * w1v + a45.y * w2v) * sc + sh);
        }
    }
    __syncthreads();

    // ---- sdw(3-tap) -> pointwise 16x16 (f32x2) -> BN -> ELU -> sum ----
    float acc[16];
    #pragma unroll
    for (int o = 0; o < 16; o++) acc[o] = 0.f;
    if (tid < 250) {
        const int t0 = tid * 2;
        ull accA[8], accB[8];
        #pragma unroll
        for (int op = 0; op < 8; op++) { accA[op] = 0; accB[op] = 0; }
        const ull* spwu = reinterpret_cast<const ull*>(s->spwp);
        #pragma unroll
        for (int c = 0; c < 16; c++) {
            const int base = c * 502 + t0;
            float2 b01 = *reinterpret_cast<const float2*>(&s->B[base]);
            float2 b23 = *reinterpret_cast<const float2*>(&s->B[base + 2]);
            float w0 = s->sdww[c * 3], w1v = s->sdww[c * 3 + 1], w2v = s->sdww[c * 3 + 2];
            float sd0 = b01.x * w0 + b01.y * w1v + b23.x * w2v;
            float sd1 = b01.y * w0 + b23.x * w1v + b23.y * w2v;
            ull d0 = pk2(sd0, sd0), d1 = pk2(sd1, sd1);
            #pragma unroll
            for (int op = 0; op < 8; op++) {
                ull w = spwu[c * 8 + op];
                accA[op] = fma2(d0, w, accA[op]);
                accB[op] = fma2(d1, w, accB[op]);
            }
        }
        const ull* bs = reinterpret_cast<const ull*>(s->bn3ps);
        const ull* bb = reinterpret_cast<const ull*>(s->bn3pb);
        #pragma unroll
        for (int op = 0; op < 8; op++) {
            ull ya = fma2(accA[op], bs[op], bb[op]);
            ull yb = fma2(accB[op], bs[op], bb[op]);
            float a0, a1, c0, c1;
            upk2(ya, a0, a1); upk2(yb, c0, c1);
            acc[2 * op]     = eluf(a0) + eluf(c0);
            acc[2 * op + 1] = eluf(a1) + eluf(c1);
        }
    }
    int lane = tid & 31, warp = tid >> 5;
    #pragma unroll
    for (int o = 0; o < 16; o++) {
        float v = acc[o];
        #pragma unroll
        for (int off = 16; off > 0; off >>= 1) v += __shfl_xor_sync(0xffffffffu, v, off);
        if (lane == 0) s->red[warp * 16 + o] = v;
    }
    __syncthreads();
    if (tid < 16) {
        float v = 0.f;
        #pragma unroll
        for (int w = 0; w < 8; w++) v += s->red[w * 16 + tid];
        s->feat[tid] = v * (1.f / 500.f);
    }
    __syncthreads();

    // ---- gat1 front-end: xl1 = feat @ W1, skip = feat @ skw^T ----
    if (tid < 128) {
        float a = 0.f;
        #pragma unroll
        for (int d = 0; d < FEAT; d++) a += s->feat[d] * __ldg(&gat1w[d * 128 + tid]);
        s->xlv[tid] = a;
        g_xl1[n * 128 + tid] = a;
    } else if (tid < 160) {
        const int f = tid - 128;
        float a = 0.f;
        #pragma unroll
        for (int d = 0; d < FEAT; d++) a += s->feat[d] * __ldg(&skipw[f * FEAT + d]);
        g_skip[n * GC + f] = a;
    }
    __syncthreads();
    if (tid < 8) {
        const int h = tid >> 1, which = tid & 1;
        const float* av = which ? adst : asrc;
        float a = 0.f;
        #pragma unroll
        for (int f2 = 0; f2 < GC; f2++) a += s->xlv[h * GC + f2] * __ldg(&av[h * GC + f2]);
        if (which) g_dv1[n * HH + h] = a;
        else       g_sv1[n * HH + h] = a;
    }
}

// ---------------------------------------------------------------------------
// Kernel 2: build padded edge rows + zero SE accumulators
// ---------------------------------------------------------------------------
__global__ __launch_bounds__(256) void graph_kernel(
    const float* __restrict__ node_embed, const int* __restrict__ edges)
{
    __shared__ float E[CC * FEAT];
    __shared__ float ee[CC * CC];
    __shared__ float rowsum[CC];
    __shared__ float msm[CC * CC];
    const int tid = threadIdx.x;

    if (tid < GC) { g_sum1[tid] = 0.f; g_sum2[tid] = 0.f; }

    for (int i = tid; i < CC * FEAT; i += 256) E[i] = node_embed[i];
    for (int i = tid; i < CC * CC; i += 256) msm[i] = 0.f;
    __syncthreads();

    for (int idx = tid; idx < CC * CC; idx += 256) {
        int i = idx >> 6, j = idx & 63;
        float v = 0.f;
        #pragma unroll
        for (int d = 0; d < FEAT; d++) v += E[i * FEAT + d] * E[j * FEAT + d];
        ee[idx] = v > 0.f ? v : 0.f;
    }
    __syncthreads();

    if (tid < CC) {
        float v = 0.f;
        #pragma unroll
        for (int j = 0; j < CC; j++) v += ee[tid * CC + j];
        rowsum[tid] = v;
    }
    {
        int e = tid;
        int src = edges[e], dst = edges[256 + e];
        atomicAdd(&msm[src * CC + dst], 1.0f);
    }
    __syncthreads();

    if (tid < CC) {
        const int i = tid;
        const float inv = 1.f / (rowsum[i] + 1e-6f);
        int d = 0;
        for (int j = 0; j < CC; j++) {
            float Mv;
            if (i == j) {
                Mv = 1.f;
            } else {
                float dyn = (ee[i * CC + j] * inv) > 0.1f ? 1.f : 0.f;
                Mv = msm[i * CC + j] + dyn;
            }
            if (Mv > 0.f) {
                g_edges[i * EST + d] = make_float2(__int_as_float(j), __logf(Mv));
                d++;
            }
        }
        g_deg[i] = d;
        for (int k = d; k < EST; k++)
            g_edges[i * EST + k] = make_float2(__int_as_float(i), -1e30f);
    }
}

// ---------------------------------------------------------------------------
// GAT layer 1: attention-only (xl/sv/dv/skip precomputed by extractor)
// ---------------------------------------------------------------------------
struct G1Smem {
    float xl[HH * SH];
    float sv[CC * HH];
    float dv[CC * HH];
    float skip[CC * GC];
    float bns[GC], bnb[GC], bias[GC], bsum[GC];
    float sbuf[256];
    float abuf[256 * 33];
    float2 earr[CC * EST];
    int   sdeg[CC];
};

__global__ __launch_bounds__(512) void gat1_kernel(
    const float* __restrict__ biasg, const float* __restrict__ bng)
{
    G1Smem* s = reinterpret_cast<G1Smem*>(smem_raw);
    const int tid = threadIdx.x;
    const int b = blockIdx.x;

    {
        const float4* src = reinterpret_cast<const float4*>(&g_xl1[b * CC * 128]);
        #pragma unroll
        for (int q = 0; q < 4; q++) {
            int idx4 = tid + q * 512;
            int idx = idx4 * 4;
            int j = idx >> 7, col = idx & 127;
            int h = col >> 5, f = col & 31;
            float4 v = src[idx4];
            *reinterpret_cast<float4*>(&s->xl[h * SH + j * SJ + f]) = v;
        }
    }
    if (tid < 256) {
        s->sv[tid] = g_sv1[b * 256 + tid];
        s->dv[tid] = g_dv1[b * 256 + tid];
    }
    {
        const float4* src = reinterpret_cast<const float4*>(&g_skip[b * CC * GC]);
        float4 v = src[tid];
        *reinterpret_cast<float4*>(&s->skip[tid * 4]) = v;
    }
    for (int i = tid; i < CC * EST; i += 512) s->earr[i] = g_edges[i];
    if (tid < CC) s->sdeg[tid] = g_deg[tid];
    if (tid < GC) {
        float g = bng[tid], bb2 = bng[GC + tid], m = bng[2 * GC + tid], v = bng[3 * GC + tid];
        float sc = g * rsqrtf(v + 1e-5f);
        s->bns[tid] = sc; s->bnb[tid] = bb2 - m * sc;
        s->bias[tid] = biasg[tid];
        s->bsum[tid] = 0.f;
    }
    __syncthreads();

    const int r = tid & 255;
    const int half = tid >> 8;
    const int i = r >> 2, h = r & 3;
    const float di = s->dv[i * HH + h];
    const int deg = s->sdeg[i];
    const float2* erow = &s->earr[i * EST];

    float mx = -1e30f;
    for (int k = 0; k < deg; k++) {
        float2 e = erow[k];
        int j = __float_as_int(e.x);
        float l = di + s->sv[j * HH + h];
        l = l > 0.f ? l : 0.2f * l;
        l += e.y;
        mx = fmaxf(mx, l);
    }
    float acc[GC];
    #pragma unroll
    for (int f = 0; f < GC; f++) acc[f] = 0.f;
    float ssum = 0.f;
    for (int k = half; k < deg; k += 2) {
        float2 e = erow[k];
        int j = __float_as_int(e.x);
        float l = di + s->sv[j * HH + h];
        l = l > 0.f ? l : 0.2f * l;
        l += e.y;
        float w = __expf(l - mx);
        ssum += w;
        const float4* xp4 = reinterpret_cast<const float4*>(&s->xl[h * SH + j * SJ]);
        #pragma unroll
        for (int m = 0; m < 8; m++) {
            float4 v = xp4[m];
            acc[m * 4 + 0] += w * v.x; acc[m * 4 + 1] += w * v.y;
            acc[m * 4 + 2] += w * v.z; acc[m * 4 + 3] += w * v.w;
        }
    }
    if (half == 1) {
        #pragma unroll
        for (int f = 0; f < GC; f++) s->abuf[r * 33 + f] = acc[f];
        s->sbuf[r] = ssum;
    }
    __syncthreads();
    if (half == 0) {
        ssum += s->sbuf[r];
        #pragma unroll
        for (int f = 0; f < GC; f++) acc[f] += s->abuf[r * 33 + f];
        const float inv = 1.f / ssum;
        #pragma unroll
        for (int f = 0; f < GC; f++) {
            float v = acc[f] * inv;
            v += __shfl_xor_sync(0xffffffffu, v, 1);
            v += __shfl_xor_sync(0xffffffffu, v, 2);
            acc[f] = v * 0.25f;
        }
        if (h == 0) {
            float vals[GC];
            #pragma unroll
            for (int f = 0; f < GC; f++) {
                float o = acc[f] + s->bias[f];
                o = o * s->bns[f] + s->bnb[f];
                float val = geluf(o + s->skip[i * GC + f]);
                g_h1[(b * CC + i) * GC + f] = val;
                vals[f] = val;
            }
            #pragma unroll
            for (int f = 0; f < GC; f++) {
                float v = vals[f];
                v += __shfl_xor_sync(0x11111111u, v, 4);
                v += __shfl_xor_sync(0x11111111u, v, 8);
                v += __shfl_xor_sync(0x11111111u, v, 16);
                if ((tid & 31) == 0) atomicAdd(&s->bsum[f], v);
            }
        }
    }
    __syncthreads();
    if (tid < GC) atomicAdd(&g_sum1[tid], s->bsum[tid]);
}

// ---------------------------------------------------------------------------
// GAT layer 2 (SE1 gate applied inline), ILP-4 GEMM with register weights
// ---------------------------------------------------------------------------
struct G2Smem {
    float xin[CC * GC];
    float W[GC * HH * GC];
    float xl[HH * SH];
    float sv[CC * HH];
    float dv[CC * HH];
    float as[HH * GC];
    float ad[HH * GC];
    float bns[GC], bnb[GC], bias[GC], bsum[GC];
    float sew1[8 * GC];
    float sew2[GC * 8];
    float gate[GC];
    float hid[8];
    float sbuf[256];
    float abuf[256 * 33];
    float2 earr[CC * EST];
    int   sdeg[CC];
};

__global__ __launch_bounds__(512) void gat2_kernel(
    const float* __restrict__ Wg, const float* __restrict__ asrc,
    const float* __restrict__ adst, const float* __restrict__ biasg,
    const float* __restrict__ bng,
    const float* __restrict__ se1w1, const float* __restrict__ se1w2)
{
    G2Smem* s = reinterpret_cast<G2Smem*>(smem_raw);
    const int tid = threadIdx.x;
    const int b = blockIdx.x;

    for (int i = tid; i < CC * GC; i += 512) s->xin[i] = g_h1[b * CC * GC + i];
    for (int i = tid; i < 4096; i += 512) s->W[i] = Wg[i];
    for (int i = tid; i < CC * EST; i += 512) s->earr[i] = g_edges[i];
    if (tid < CC) s->sdeg[tid] = g_deg[tid];
    if (tid < 128) { s->as[tid] = asrc[tid]; s->ad[tid] = adst[tid]; }
    if (tid < 256) { s->sew1[tid] = se1w1[tid]; s->sew2[tid] = se1w2[tid]; }
    if (tid < GC) {
        float g = bng[tid], bb2 = bng[GC + tid], m = bng[2 * GC + tid], v = bng[3 * GC + tid];
        float sc = g * rsqrtf(v + 1e-5f);
        s->bns[tid] = sc; s->bnb[tid] = bb2 - m * sc;
        s->bias[tid] = biasg[tid];
        s->bsum[tid] = 0.f;
    }
    __syncthreads();

    if (tid < 8) {
        float a = 0.f;
        #pragma unroll
        for (int f = 0; f < GC; f++) a += (g_sum1[f] * (1.f / (float)NSIG)) * s->sew1[tid * GC + f];
        s->hid[tid] = a > 0.f ? a : 0.f;
    }
    __syncthreads();
    if (tid < GC) {
        float a = 0.f;
        #pragma unroll
        for (int k = 0; k < 8; k++) a += s->hid[k] * s->sew2[tid * 8 + k];
        s->gate[tid] = 1.f / (1.f + __expf(-a));
    }
    __syncthreads();
    for (int idx = tid; idx < CC * GC; idx += 512) s->xin[idx] *= s->gate[idx & 31];
    __syncthreads();

    {
        const int col = tid & 127;
        const int jg = tid >> 7;
        const int h = col >> 5, f = col & 31;
        float wreg[GC];
        #pragma unroll
        for (int d = 0; d < GC; d++) wreg[d] = s->W[d * 128 + col];
        #pragma unroll
        for (int q = 0; q < 4; q++) {
            const int j0 = jg * 16 + q * 4;
            float a0 = 0.f, a1 = 0.f, a2 = 0.f, a3 = 0.f;
            #pragma unroll
            for (int dc = 0; dc < 8; dc++) {
                const float4 x0 = *reinterpret_cast<const float4*>(&s->xin[(j0 + 0) * GC + dc * 4]);
                const float4 x1 = *reinterpret_cast<const float4*>(&s->xin[(j0 + 1) * GC + dc * 4]);
                const float4 x2 = *reinterpret_cast<const float4*>(&s->xin[(j0 + 2) * GC + dc * 4]);
                const float4 x3 = *reinterpret_cast<const float4*>(&s->xin[(j0 + 3) * GC + dc * 4]);
                const float w0 = wreg[dc * 4], w1 = wreg[dc * 4 + 1];
                const float w2 = wreg[dc * 4 + 2], w3 = wreg[dc * 4 + 3];
                a0 += x0.x * w0 + x0.y * w1 + x0.z * w2 + x0.w * w3;
                a1 += x1.x * w0 + x1.y * w1 + x1.z * w2 + x1.w * w3;
                a2 += x2.x * w0 + x2.y * w1 + x2.z * w2 + x2.w * w3;
                a3 += x3.x * w0 + x3.y * w1 + x3.z * w2 + x3.w * w3;
            }
            s->xl[h * SH + (j0 + 0) * SJ + f] = a0;
            s->xl[h * SH + (j0 + 1) * SJ + f] = a1;
            s->xl[h * SH + (j0 + 2) * SJ + f] = a2;
            s->xl[h * SH + (j0 + 3) * SJ + f] = a3;
        }
    }
    __syncthreads();

    if (tid < 256) {
        int j = tid >> 2, h = tid & 3;
        const float4* xp4 = reinterpret_cast<const float4*>(&s->xl[h * SH + j * SJ]);
        const float4* as4 = reinterpret_cast<const float4*>(&s->as[h * GC]);
        const float4* ad4 = reinterpret_cast<const float4*>(&s->ad[h * GC]);
        float sa = 0.f, da = 0.f;
        #pragma unroll
        for (int m = 0; m < 8; m++) {
            float4 xv = xp4[m], av = as4[m], dvv = ad4[m];
            sa += xv.x * av.x + xv.y * av.y + xv.z * av.z + xv.w * av.w;
            da += xv.x * dvv.x + xv.y * dvv.y + xv.z * dvv.z + xv.w * dvv.w;
        }
        s->sv[j * HH + h] = sa;
        s->dv[j * HH + h] = da;
    }
    __syncthreads();

    const int r = tid & 255;
    const int half = tid >> 8;
    const int i = r >> 2, h = r & 3;
    const float di = s->dv[i * HH + h];
    const int deg = s->sdeg[i];
    const float2* erow = &s->earr[i * EST];

    float mx = -1e30f;
    for (int k = 0; k < deg; k++) {
        float2 e = erow[k];
        int j = __float_as_int(e.x);
        float l = di + s->sv[j * HH + h];
        l = l > 0.f ? l : 0.2f * l;
        l += e.y;
        mx = fmaxf(mx, l);
    }
    float acc[GC];
    #pragma unroll
    for (int f = 0; f < GC; f++) acc[f] = 0.f;
    float ssum = 0.f;
    for (int k = half; k < deg; k += 2) {
        float2 e = erow[k];
        int j = __float_as_int(e.x);
        float l = di + s->sv[j * HH + h];
        l = l > 0.f ? l : 0.2f * l;
        l += e.y;
        float w = __expf(l - mx);
        ssum += w;
        const float4* xp4 = reinterpret_cast<const float4*>(&s->xl[h * SH + j * SJ]);
        #pragma unroll
        for (int m = 0; m < 8; m++) {
            float4 v = xp4[m];
            acc[m * 4 + 0] += w * v.x; acc[m * 4 + 1] += w * v.y;
            acc[m * 4 + 2] += w * v.z; acc[m * 4 + 3] += w * v.w;
        }
    }
    if (half == 1) {
        #pragma unroll
        for (int f = 0; f < GC; f++) s->abuf[r * 33 + f] = acc[f];
        s->sbuf[r] = ssum;
    }
    __syncthreads();
    if (half == 0) {
        ssum += s->sbuf[r];
        #pragma unroll
        for (int f = 0; f < GC; f++) acc[f] += s->abuf[r * 33 + f];
        const float inv = 1.f / ssum;
        #pragma unroll
        for (int f = 0; f < GC; f++) {
            float v = acc[f] * inv;
            v += __shfl_xor_sync(0xffffffffu, v, 1);
            v += __shfl_xor_sync(0xffffffffu, v, 2);
            acc[f] = v * 0.25f;
        }
        if (h == 0) {
            float vals[GC];
            #pragma unroll
            for (int f = 0; f < GC; f++) {
                float o = acc[f] + s->bias[f];
                o = o * s->bns[f] + s->bnb[f];
                vals[f] = geluf(o + s->xin[i * GC + f]);
            }
            #pragma unroll
            for (int f = 0; f < GC; f++) {
                float v = vals[f];
                v += __shfl_xor_sync(0x11111111u, v, 4);
                v += __shfl_xor_sync(0x11111111u, v, 8);
                v += __shfl_xor_sync(0x11111111u, v, 16);
                if ((tid & 31) == 0) atomicAdd(&s->bsum[f], v);
            }
        }
    }
    __syncthreads();
    if (tid < GC) {
        atomicAdd(&g_sum2[tid], s->bsum[tid]);
        g_pooled[b * GC + tid] = s->bsum[tid] * (1.f / (float)CC);
    }
}

// ---------------------------------------------------------------------------
// Final: SE2 gate + classifier
// ---------------------------------------------------------------------------
__global__ __launch_bounds__(256) void final_kernel(
    const float* __restrict__ se2w1, const float* __restrict__ se2w2,
    const float* __restrict__ clfw, const float* __restrict__ clfb,
    float* __restrict__ out)
{
    __shared__ float hid[8];
    __shared__ float gate[GC];
    const int tid = threadIdx.x;
    if (tid < 8) {
        float a = 0.f;
        #pragma unroll
        for (int f = 0; f < GC; f++) a += (g_sum2[f] * (1.f / (float)NSIG)) * se2w1[tid * GC + f];
        hid[tid] = a > 0.f ? a : 0.f;
    }
    __syncthreads();
    if (tid < GC) {
        float a = 0.f;
        #pragma unroll
        for (int k = 0; k < 8; k++) a += hid[k] * se2w2[tid * 8 + k];
        gate[tid] = 1.f / (1.f + __expf(-a));
    }
    __syncthreads();
    {
        int b = tid >> 1, n = tid & 1;
        float a = clfb[n];
        #pragma unroll
        for (int f = 0; f < GC; f++)
            a += g_pooled[b * GC + f] * gate[f] * clfw[n * GC + f];
        out[b * NCLS + n] = a;
    }
}

// ---------------------------------------------------------------------------
// kernel_launch
// ---------------------------------------------------------------------------
extern "C" void kernel_launch(void* const* d_in, const int* in_sizes, int n_in,
                              void* d_out, int out_size)
{
    const float* x         = (const float*)d_in[0];
    const int*   edges     = (const int*)  d_in[1];
    const float* conv1_w   = (const float*)d_in[2];
    const float* bn_c1     = (const float*)d_in[3];
    const float* dw_w      = (const float*)d_in[4];
    const float* bn_c2     = (const float*)d_in[5];
    const float* sdw_w     = (const float*)d_in[6];
    const float* spw_w     = (const float*)d_in[7];
    const float* bn_c3     = (const float*)d_in[8];
    const float* node_emb  = (const float*)d_in[9];
    const float* gat1_w    = (const float*)d_in[10];
    const float* gat1_as   = (const float*)d_in[11];
    const float* gat1_ad   = (const float*)d_in[12];
    const float* gat1_b    = (const float*)d_in[13];
    const float* bn_g1     = (const float*)d_in[14];
    const float* skip1_w   = (const float*)d_in[15];
    const float* se1_w1    = (const float*)d_in[16];
    const float* se1_w2    = (const float*)d_in[17];
    const float* gat2_w    = (const float*)d_in[18];
    const float* gat2_as   = (const float*)d_in[19];
    const float* gat2_ad   = (const float*)d_in[20];
    const float* gat2_b    = (const float*)d_in[21];
    const float* bn_g2     = (const float*)d_in[22];
    const float* se2_w1    = (const float*)d_in[23];
    const float* se2_w2    = (const float*)d_in[24];
    const float* clf_w     = (const float*)d_in[25];
    const float* clf_b     = (const float*)d_in[26];
    float* out = (float*)d_out;

    cudaFuncSetAttribute(extractor_kernel, cudaFuncAttributeMaxDynamicSharedMemorySize, (int)sizeof(ExSmem));
    cudaFuncSetAttribute(gat1_kernel,      cudaFuncAttributeMaxDynamicSharedMemorySize, (int)sizeof(G1Smem));
    cudaFuncSetAttribute(gat2_kernel,      cudaFuncAttributeMaxDynamicSharedMemorySize, (int)sizeof(G2Smem));

    extractor_kernel<<<NSIG, 256, sizeof(ExSmem)>>>(x, conv1_w, bn_c1, dw_w, bn_c2,
                                                    sdw_w, spw_w, bn_c3,
                                                    gat1_w, gat1_as, gat1_ad, skip1_w);
    graph_kernel<<<1, 256>>>(node_emb, edges);
    gat1_kernel<<<BB, 512, sizeof(G1Smem)>>>(gat1_b, bn_g1);
    gat2_kernel<<<BB, 512, sizeof(G2Smem)>>>(gat2_w, gat2_as, gat2_ad, gat2_b, bn_g2, se1_w1, se1_w2);
    final_kernel<<<1, 256>>>(se2_w1, se2_w2, clf_w, clf_b, out);
}

// round 16
// speedup vs baseline: 1.0741x; 1.0500x over previous
#include <cuda_runtime.h>
#include <math.h>
#include <stdint.h>

// ---------------------------------------------------------------------------
// Problem constants
// ---------------------------------------------------------------------------
#define BB 128
#define CC 64
#define TT 500
#define NSIG (BB*CC)          // 8192
#define FEAT 16
#define GC 32
#define HH 4
#define NCLS 2

// xl layout strides (conflict-free LDS)
#define SJ 36
#define SH 2312
#define EST 65

// ---------------------------------------------------------------------------
// Device scratch
// ---------------------------------------------------------------------------
__device__ float g_xl1[NSIG * HH * GC];
__device__ float g_skip[NSIG * GC];
__device__ float g_sv1[NSIG * HH];
__device__ float g_dv1[NSIG * HH];
__device__ float g_h1[NSIG * GC];
__device__ float g_sum1[GC];
__device__ float g_sum2[GC];
__device__ float g_pooled[BB * GC];
__device__ int    g_deg[CC];
__device__ float2 g_edges[CC * EST];

__device__ __forceinline__ float eluf(float v) {
    return v > 0.f ? v : (__expf(v) - 1.f);
}
__device__ __forceinline__ float geluf(float v) {
    return 0.5f * v * (1.f + erff(v * 0.70710678118654752f));
}

// ---- packed f32x2 helpers ----
typedef unsigned long long ull;
__device__ __forceinline__ ull pk2(float lo, float hi) {
    ull r;
    asm("mov.b64 %0, {%1, %2};" : "=l"(r) : "f"(lo), "f"(hi));
    return r;
}
__device__ __forceinline__ void upk2(ull v, float& lo, float& hi) {
    asm("mov.b64 {%0, %1}, %2;" : "=f"(lo), "=f"(hi) : "l"(v));
}
__device__ __forceinline__ ull fma2(ull a, ull b, ull c) {
    ull d;
    asm("fma.rn.f32x2 %0, %1, %2, %3;" : "=l"(d) : "l"(a), "l"(b), "l"(c));
    return d;
}

// ---------------------------------------------------------------------------
// Kernel 1: fused feature extractor + gat1 front-end + (block NSIG) graph build.
// One block = one signal/node; extra block builds the adjacency.
// conv1: 2 groups x 2 channel-pairs, rolling dup-window (low reg pressure).
// ---------------------------------------------------------------------------
struct ExSmem {
    float sx[528];            // padded input X (physical = t + 12)
    float A[16 * 502];        // conv1 out, halo-1 (physical = t + 1)
    float B[16 * 502];        // dw out, halo-1
    float2 w1p[200];          // conv1 weights paired over channels: [k*8+cp]
    float2 spwp[128];         // pointwise weights paired over out-ch
    float2 bn1ps[8], bn1pb[8];
    float2 bn3ps[8], bn3pb[8];
    float dww[48];
    float sdww[48];
    float bn2s[16], bn2b[16];
    float red[8 * 16];
    float feat[16];
    float xlv[128];
};

extern __shared__ unsigned char smem_raw[];

__global__ __launch_bounds__(256) void extractor_kernel(
    const float* __restrict__ x,
    const float* __restrict__ conv1_w, const float* __restrict__ bn_c1,
    const float* __restrict__ dw_w,    const float* __restrict__ bn_c2,
    const float* __restrict__ sdw_w,   const float* __restrict__ spw_w,
    const float* __restrict__ bn_c3,
    const float* __restrict__ gat1w,   const float* __restrict__ asrc,
    const float* __restrict__ adst,    const float* __restrict__ skipw,
    const float* __restrict__ node_embed, const int* __restrict__ edges)
{
    const int tid = threadIdx.x;
    const int n = blockIdx.x;

    // ================= graph-builder block =================
    if (n == NSIG) {
        float* E      = reinterpret_cast<float*>(smem_raw);        // 1024
        float* ee     = E + 1024;                                  // 4096
        float* msm    = ee + 4096;                                 // 4096
        float* rowsum = msm + 4096;                                // 64

        if (tid < GC) { g_sum1[tid] = 0.f; g_sum2[tid] = 0.f; }

        for (int i = tid; i < CC * FEAT; i += 256) E[i] = node_embed[i];
        for (int i = tid; i < CC * CC; i += 256) msm[i] = 0.f;
        __syncthreads();

        for (int idx = tid; idx < CC * CC; idx += 256) {
            int i = idx >> 6, j = idx & 63;
            float v = 0.f;
            #pragma unroll
            for (int d = 0; d < FEAT; d++) v += E[i * FEAT + d] * E[j * FEAT + d];
            ee[idx] = v > 0.f ? v : 0.f;
        }
        __syncthreads();

        if (tid < CC) {
            float v = 0.f;
            #pragma unroll
            for (int j = 0; j < CC; j++) v += ee[tid * CC + j];
            rowsum[tid] = v;
        }
        {
            int e = tid;
            int src = edges[e], dst = edges[256 + e];
            atomicAdd(&msm[src * CC + dst], 1.0f);
        }
        __syncthreads();

        if (tid < CC) {
            const int i = tid;
            const float inv = 1.f / (rowsum[i] + 1e-6f);
            int d = 0;
            for (int j = 0; j < CC; j++) {
                float Mv;
                if (i == j) {
                    Mv = 1.f;
                } else {
                    float dyn = (ee[i * CC + j] * inv) > 0.1f ? 1.f : 0.f;
                    Mv = msm[i * CC + j] + dyn;
                }
                if (Mv > 0.f) {
                    g_edges[i * EST + d] = make_float2(__int_as_float(j), __logf(Mv));
                    d++;
                }
            }
            g_deg[i] = d;
            for (int k = d; k < EST; k++)
                g_edges[i * EST + k] = make_float2(__int_as_float(i), -1e30f);
        }
        return;
    }

    // ================= extractor blocks =================
    ExSmem* s = reinterpret_cast<ExSmem*>(smem_raw);

    // ---- cooperative loads ----
    for (int i = tid; i < 528; i += 256) {
        int t = i - 12;
        s->sx[i] = (t >= 0 && t < TT) ? x[n * TT + t] : 0.f;
    }
    {   // paired conv1 weights: w1p[k*8+cp] = (w[2cp][k], w[2cp+1][k])
        int i = tid;
        if (i < 200) {
            int k = i >> 3, cp = i & 7;
            s->w1p[i] = make_float2(conv1_w[(2 * cp) * 25 + k],
                                    conv1_w[(2 * cp + 1) * 25 + k]);
        }
    }
    if (tid < 128) {   // paired pointwise: spwp[c*8+op] = (w[2op][c], w[2op+1][c])
        int c = tid >> 3, op = tid & 7;
        s->spwp[tid] = make_float2(spw_w[(2 * op) * 16 + c],
                                   spw_w[(2 * op + 1) * 16 + c]);
    }
    if (tid < 48) { s->dww[tid] = dw_w[tid]; s->sdww[tid] = sdw_w[tid]; }
    if (tid >= 208 && tid < 224) {
        int f = tid - 208;
        float g = bn_c2[f], b = bn_c2[16 + f], m = bn_c2[32 + f], v = bn_c2[48 + f];
        float sc = g * rsqrtf(v + 1e-5f);
        s->bn2s[f] = sc; s->bn2b[f] = b - m * sc;
    } else if (tid >= 224 && tid < 232) {
        int p = tid - 224;
        float sc0, sh0, sc1, sh1;
        {   int c = 2 * p;
            float g = bn_c1[c], b = bn_c1[16 + c], m = bn_c1[32 + c], v = bn_c1[48 + c];
            sc0 = g * rsqrtf(v + 1e-5f); sh0 = b - m * sc0; }
        {   int c = 2 * p + 1;
            float g = bn_c1[c], b = bn_c1[16 + c], m = bn_c1[32 + c], v = bn_c1[48 + c];
            sc1 = g * rsqrtf(v + 1e-5f); sh1 = b - m * sc1; }
        s->bn1ps[p] = make_float2(sc0, sc1); s->bn1pb[p] = make_float2(sh0, sh1);
    } else if (tid >= 232 && tid < 240) {
        int p = tid - 232;
        float sc0, sh0, sc1, sh1;
        {   int c = 2 * p;
            float g = bn_c3[c], b = bn_c3[16 + c], m = bn_c3[32 + c], v = bn_c3[48 + c];
            sc0 = g * rsqrtf(v + 1e-5f); sh0 = b - m * sc0; }
        {   int c = 2 * p + 1;
            float g = bn_c3[c], b = bn_c3[16 + c], m = bn_c3[32 + c], v = bn_c3[48 + c];
            sc1 = g * rsqrtf(v + 1e-5f); sh1 = b - m * sc1; }
        s->bn3ps[p] = make_float2(sc0, sc1); s->bn3pb[p] = make_float2(sh0, sh1);
    }
    {   // zero halos of A and B
        int q = tid - 144;
        if (q >= 0 && q < 64) {
            int half = q >> 5, r = q & 31;
            int c = r >> 1, side = r & 1;
            float* arr = half ? s->B : s->A;
            arr[c * 502 + side * 501] = 0.f;
        }
    }
    __syncthreads();

    const int g = tid & 127;
    const int cb = tid >> 7;

    // ---- conv1 (25-tap) + BN + ELU ----
    if (g < 125) {
        const int t0 = g << 2;
        float xv[28];
        const float4* sx4 = reinterpret_cast<const float4*>(s->sx);
        #pragma unroll
        for (int m = 0; m < 7; m++) {
            float4 v = sx4[(t0 >> 2) + m];
            xv[m * 4 + 0] = v.x; xv[m * 4 + 1] = v.y;
            xv[m * 4 + 2] = v.z; xv[m * 4 + 3] = v.w;
        }
        const ull* w1u = reinterpret_cast<const ull*>(s->w1p);
        const ull* bs  = reinterpret_cast<const ull*>(s->bn1ps);
        const ull* bb  = reinterpret_cast<const ull*>(s->bn1pb);
        #pragma unroll
        for (int pp = 0; pp < 2; pp++) {
            const int cp0 = (cb << 2) + pp * 2;
            const int cp1 = cp0 + 1;
            ull a0 = 0, a1 = 0, a2 = 0, a3 = 0;
            ull b0 = 0, b1 = 0, b2 = 0, b3 = 0;
            ull d0 = pk2(xv[0], xv[0]), d1 = pk2(xv[1], xv[1]);
            ull d2 = pk2(xv[2], xv[2]), d3 = pk2(xv[3], xv[3]);
            #pragma unroll
            for (int k = 0; k < 25; k++) {
                ull w0 = w1u[k * 8 + cp0];
                ull w1 = w1u[k * 8 + cp1];
                a0 = fma2(d0, w0, a0); a1 = fma2(d1, w0, a1);
                a2 = fma2(d2, w0, a2); a3 = fma2(d3, w0, a3);
                b0 = fma2(d0, w1, b0); b1 = fma2(d1, w1, b1);
                b2 = fma2(d2, w1, b2); b3 = fma2(d3, w1, b3);
                if (k < 24) {
                    d0 = d1; d1 = d2; d2 = d3;
                    d3 = pk2(xv[k + 4], xv[k + 4]);
                }
            }
            {   // epilogue cp0
                ull sc = bs[cp0], sh = bb[cp0];
                a0 = fma2(a0, sc, sh); a1 = fma2(a1, sc, sh);
                a2 = fma2(a2, sc, sh); a3 = fma2(a3, sc, sh);
                float lo, hi;
                float* A0 = &s->A[(2 * cp0) * 502 + 1 + t0];
                float* A1 = &s->A[(2 * cp0 + 1) * 502 + 1 + t0];
                upk2(a0, lo, hi); A0[0] = eluf(lo); A1[0] = eluf(hi);
                upk2(a1, lo, hi); A0[1] = eluf(lo); A1[1] = eluf(hi);
                upk2(a2, lo, hi); A0[2] = eluf(lo); A1[2] = eluf(hi);
                upk2(a3, lo, hi); A0[3] = eluf(lo); A1[3] = eluf(hi);
            }
            {   // epilogue cp1
                ull sc = bs[cp1], sh = bb[cp1];
                b0 = fma2(b0, sc, sh); b1 = fma2(b1, sc, sh);
                b2 = fma2(b2, sc, sh); b3 = fma2(b3, sc, sh);
                float lo, hi;
                float* A0 = &s->A[(2 * cp1) * 502 + 1 + t0];
                float* A1 = &s->A[(2 * cp1 + 1) * 502 + 1 + t0];
                upk2(b0, lo, hi); A0[0] = eluf(lo); A1[0] = eluf(hi);
                upk2(b1, lo, hi); A0[1] = eluf(lo); A1[1] = eluf(hi);
                upk2(b2, lo, hi); A0[2] = eluf(lo); A1[2] = eluf(hi);
                upk2(b3, lo, hi); A0[3] = eluf(lo); A1[3] = eluf(hi);
            }
        }
    }
    __syncthreads();

    // ---- depthwise 3-tap + BN + ELU ----
    if (g < 125) {
        const int t0 = g << 2;
        #pragma unroll
        for (int ci = 0; ci < 8; ci++) {
            const int c = cb * 8 + ci;
            const int base = c * 502 + t0;
            float2 a01 = *reinterpret_cast<const float2*>(&s->A[base]);
            float2 a23 = *reinterpret_cast<const float2*>(&s->A[base + 2]);
            float2 a45 = *reinterpret_cast<const float2*>(&s->A[base + 4]);
            float w0 = s->dww[c * 3], w1v = s->dww[c * 3 + 1], w2v = s->dww[c * 3 + 2];
            float sc = s->bn2s[c], sh = s->bn2b[c];
            float* Bp = &s->B[base + 1];
            Bp[0] = eluf((a01.x * w0 + a01.y * w1v + a23.x * w2v) * sc + sh);
            Bp[1] = eluf((a01.y * w0 + a23.x * w1v + a23.y * w2v) * sc + sh);
            Bp[2] = eluf((a23.x * w0 + a23.y * w1v + a45.x * w2v) * sc + sh);
            Bp[3] = eluf((a23.y * w0 + a45.x * w1v + a45.y * w2v) * sc + sh);
        }
    }
    __syncthreads();

    // ---- sdw(3-tap) -> pointwise 16x16 (f32x2) -> BN -> ELU -> sum ----
    float acc[16];
    #pragma unroll
    for (int o = 0; o < 16; o++) acc[o] = 0.f;
    if (tid < 250) {
        const int t0 = tid * 2;
        ull accA[8], accB[8];
        #pragma unroll
        for (int op = 0; op < 8; op++) { accA[op] = 0; accB[op] = 0; }
        const ull* spwu = reinterpret_cast<const ull*>(s->spwp);
        #pragma unroll
        for (int c = 0; c < 16; c++) {
            const int base = c * 502 + t0;
            float2 b01 = *reinterpret_cast<const float2*>(&s->B[base]);
            float2 b23 = *reinterpret_cast<const float2*>(&s->B[base + 2]);
            float w0 = s->sdww[c * 3], w1v = s->sdww[c * 3 + 1], w2v = s->sdww[c * 3 + 2];
            float sd0 = b01.x * w0 + b01.y * w1v + b23.x * w2v;
            float sd1 = b01.y * w0 + b23.x * w1v + b23.y * w2v;
            ull d0 = pk2(sd0, sd0), d1 = pk2(sd1, sd1);
            #pragma unroll
            for (int op = 0; op < 8; op++) {
                ull w = spwu[c * 8 + op];
                accA[op] = fma2(d0, w, accA[op]);
                accB[op] = fma2(d1, w, accB[op]);
            }
        }
        const ull* bs = reinterpret_cast<const ull*>(s->bn3ps);
        const ull* bb = reinterpret_cast<const ull*>(s->bn3pb);
        #pragma unroll
        for (int op = 0; op < 8; op++) {
            ull ya = fma2(accA[op], bs[op], bb[op]);
            ull yb = fma2(accB[op], bs[op], bb[op]);
            float a0, a1, c0, c1;
            upk2(ya, a0, a1); upk2(yb, c0, c1);
            acc[2 * op]     = eluf(a0) + eluf(c0);
            acc[2 * op + 1] = eluf(a1) + eluf(c1);
        }
    }
    int lane = tid & 31, warp = tid >> 5;
    #pragma unroll
    for (int o = 0; o < 16; o++) {
        float v = acc[o];
        #pragma unroll
        for (int off = 16; off > 0; off >>= 1) v += __shfl_xor_sync(0xffffffffu, v, off);
        if (lane == 0) s->red[warp * 16 + o] = v;
    }
    __syncthreads();
    if (tid < 16) {
        float v = 0.f;
        #pragma unroll
        for (int w = 0; w < 8; w++) v += s->red[w * 16 + tid];
        s->feat[tid] = v * (1.f / 500.f);
    }
    __syncthreads();

    // ---- gat1 front-end: xl1 = feat @ W1, skip = feat @ skw^T ----
    if (tid < 128) {
        float a = 0.f;
        #pragma unroll
        for (int d = 0; d < FEAT; d++) a += s->feat[d] * __ldg(&gat1w[d * 128 + tid]);
        s->xlv[tid] = a;
        g_xl1[n * 128 + tid] = a;
    } else if (tid < 160) {
        const int f = tid - 128;
        float a = 0.f;
        #pragma unroll
        for (int d = 0; d < FEAT; d++) a += s->feat[d] * __ldg(&skipw[f * FEAT + d]);
        g_skip[n * GC + f] = a;
    }
    __syncthreads();
    if (tid < 8) {
        const int h = tid >> 1, which = tid & 1;
        const float* av = which ? adst : asrc;
        float a = 0.f;
        #pragma unroll
        for (int f2 = 0; f2 < GC; f2++) a += s->xlv[h * GC + f2] * __ldg(&av[h * GC + f2]);
        if (which) g_dv1[n * HH + h] = a;
        else       g_sv1[n * HH + h] = a;
    }
}

// ---------------------------------------------------------------------------
// GAT layer 1: attention-only (xl/sv/dv/skip precomputed by extractor)
// ---------------------------------------------------------------------------
struct G1Smem {
    float xl[HH * SH];
    float sv[CC * HH];
    float dv[CC * HH];
    float skip[CC * GC];
    float bns[GC], bnb[GC], bias[GC], bsum[GC];
    float sbuf[256];
    float abuf[256 * 33];
    float2 earr[CC * EST];
    int   sdeg[CC];
};

__global__ __launch_bounds__(512) void gat1_kernel(
    const float* __restrict__ biasg, const float* __restrict__ bng)
{
    G1Smem* s = reinterpret_cast<G1Smem*>(smem_raw);
    const int tid = threadIdx.x;
    const int b = blockIdx.x;

    {
        const float4* src = reinterpret_cast<const float4*>(&g_xl1[b * CC * 128]);
        #pragma unroll
        for (int q = 0; q < 4; q++) {
            int idx4 = tid + q * 512;
            int idx = idx4 * 4;
            int j = idx >> 7, col = idx & 127;
            int h = col >> 5, f = col & 31;
            float4 v = src[idx4];
            *reinterpret_cast<float4*>(&s->xl[h * SH + j * SJ + f]) = v;
        }
    }
    if (tid < 256) {
        s->sv[tid] = g_sv1[b * 256 + tid];
        s->dv[tid] = g_dv1[b * 256 + tid];
    }
    {
        const float4* src = reinterpret_cast<const float4*>(&g_skip[b * CC * GC]);
        float4 v = src[tid];
        *reinterpret_cast<float4*>(&s->skip[tid * 4]) = v;
    }
    for (int i = tid; i < CC * EST; i += 512) s->earr[i] = g_edges[i];
    if (tid < CC) s->sdeg[tid] = g_deg[tid];
    if (tid < GC) {
        float g = bng[tid], bb2 = bng[GC + tid], m = bng[2 * GC + tid], v = bng[3 * GC + tid];
        float sc = g * rsqrtf(v + 1e-5f);
        s->bns[tid] = sc; s->bnb[tid] = bb2 - m * sc;
        s->bias[tid] = biasg[tid];
        s->bsum[tid] = 0.f;
    }
    __syncthreads();

    const int r = tid & 255;
    const int half = tid >> 8;
    const int i = r >> 2, h = r & 3;
    const float di = s->dv[i * HH + h];
    const int deg = s->sdeg[i];
    const float2* erow = &s->earr[i * EST];

    float mx = -1e30f;
    for (int k = 0; k < deg; k++) {
        float2 e = erow[k];
        int j = __float_as_int(e.x);
        float l = di + s->sv[j * HH + h];
        l = l > 0.f ? l : 0.2f * l;
        l += e.y;
        mx = fmaxf(mx, l);
    }
    float acc[GC];
    #pragma unroll
    for (int f = 0; f < GC; f++) acc[f] = 0.f;
    float ssum = 0.f;
    for (int k = half; k < deg; k += 2) {
        float2 e = erow[k];
        int j = __float_as_int(e.x);
        float l = di + s->sv[j * HH + h];
        l = l > 0.f ? l : 0.2f * l;
        l += e.y;
        float w = __expf(l - mx);
        ssum += w;
        const float4* xp4 = reinterpret_cast<const float4*>(&s->xl[h * SH + j * SJ]);
        #pragma unroll
        for (int m = 0; m < 8; m++) {
            float4 v = xp4[m];
            acc[m * 4 + 0] += w * v.x; acc[m * 4 + 1] += w * v.y;
            acc[m * 4 + 2] += w * v.z; acc[m * 4 + 3] += w * v.w;
        }
    }
    if (half == 1) {
        #pragma unroll
        for (int f = 0; f < GC; f++) s->abuf[r * 33 + f] = acc[f];
        s->sbuf[r] = ssum;
    }
    __syncthreads();
    if (half == 0) {
        ssum += s->sbuf[r];
        #pragma unroll
        for (int f = 0; f < GC; f++) acc[f] += s->abuf[r * 33 + f];
        const float inv = 1.f / ssum;
        #pragma unroll
        for (int f = 0; f < GC; f++) {
            float v = acc[f] * inv;
            v += __shfl_xor_sync(0xffffffffu, v, 1);
            v += __shfl_xor_sync(0xffffffffu, v, 2);
            acc[f] = v * 0.25f;
        }
        if (h == 0) {
            float vals[GC];
            #pragma unroll
            for (int f = 0; f < GC; f++) {
                float o = acc[f] + s->bias[f];
                o = o * s->bns[f] + s->bnb[f];
                float val = geluf(o + s->skip[i * GC + f]);
                g_h1[(b * CC + i) * GC + f] = val;
                vals[f] = val;
            }
            #pragma unroll
            for (int f = 0; f < GC; f++) {
                float v = vals[f];
                v += __shfl_xor_sync(0x11111111u, v, 4);
                v += __shfl_xor_sync(0x11111111u, v, 8);
                v += __shfl_xor_sync(0x11111111u, v, 16);
                if ((tid & 31) == 0) atomicAdd(&s->bsum[f], v);
            }
        }
    }
    __syncthreads();
    if (tid < GC) atomicAdd(&g_sum1[tid], s->bsum[tid]);
}

// ---------------------------------------------------------------------------
// GAT layer 2 (SE1 gate applied inline), ILP-4 GEMM with register weights
// ---------------------------------------------------------------------------
struct G2Smem {
    float xin[CC * GC];
    float W[GC * HH * GC];
    float xl[HH * SH];
    float sv[CC * HH];
    float dv[CC * HH];
    float as[HH * GC];
    float ad[HH * GC];
    float bns[GC], bnb[GC], bias[GC], bsum[GC];
    float sew1[8 * GC];
    float sew2[GC * 8];
    float gate[GC];
    float hid[8];
    float sbuf[256];
    float abuf[256 * 33];
    float2 earr[CC * EST];
    int   sdeg[CC];
};

__global__ __launch_bounds__(512) void gat2_kernel(
    const float* __restrict__ Wg, const float* __restrict__ asrc,
    const float* __restrict__ adst, const float* __restrict__ biasg,
    const float* __restrict__ bng,
    const float* __restrict__ se1w1, const float* __restrict__ se1w2)
{
    G2Smem* s = reinterpret_cast<G2Smem*>(smem_raw);
    const int tid = threadIdx.x;
    const int b = blockIdx.x;

    for (int i = tid; i < CC * GC; i += 512) s->xin[i] = g_h1[b * CC * GC + i];
    for (int i = tid; i < 4096; i += 512) s->W[i] = Wg[i];
    for (int i = tid; i < CC * EST; i += 512) s->earr[i] = g_edges[i];
    if (tid < CC) s->sdeg[tid] = g_deg[tid];
    if (tid < 128) { s->as[tid] = asrc[tid]; s->ad[tid] = adst[tid]; }
    if (tid < 256) { s->sew1[tid] = se1w1[tid]; s->sew2[tid] = se1w2[tid]; }
    if (tid < GC) {
        float g = bng[tid], bb2 = bng[GC + tid], m = bng[2 * GC + tid], v = bng[3 * GC + tid];
        float sc = g * rsqrtf(v + 1e-5f);
        s->bns[tid] = sc; s->bnb[tid] = bb2 - m * sc;
        s->bias[tid] = biasg[tid];
        s->bsum[tid] = 0.f;
    }
    __syncthreads();

    if (tid < 8) {
        float a = 0.f;
        #pragma unroll
        for (int f = 0; f < GC; f++) a += (g_sum1[f] * (1.f / (float)NSIG)) * s->sew1[tid * GC + f];
        s->hid[tid] = a > 0.f ? a : 0.f;
    }
    __syncthreads();
    if (tid < GC) {
        float a = 0.f;
        #pragma unroll
        for (int k = 0; k < 8; k++) a += s->hid[k] * s->sew2[tid * 8 + k];
        s->gate[tid] = 1.f / (1.f + __expf(-a));
    }
    __syncthreads();
    for (int idx = tid; idx < CC * GC; idx += 512) s->xin[idx] *= s->gate[idx & 31];
    __syncthreads();

    {
        const int col = tid & 127;
        const int jg = tid >> 7;
        const int h = col >> 5, f = col & 31;
        float wreg[GC];
        #pragma unroll
        for (int d = 0; d < GC; d++) wreg[d] = s->W[d * 128 + col];
        #pragma unroll
        for (int q = 0; q < 4; q++) {
            const int j0 = jg * 16 + q * 4;
            float a0 = 0.f, a1 = 0.f, a2 = 0.f, a3 = 0.f;
            #pragma unroll
            for (int dc = 0; dc < 8; dc++) {
                const float4 x0 = *reinterpret_cast<const float4*>(&s->xin[(j0 + 0) * GC + dc * 4]);
                const float4 x1 = *reinterpret_cast<const float4*>(&s->xin[(j0 + 1) * GC + dc * 4]);
                const float4 x2 = *reinterpret_cast<const float4*>(&s->xin[(j0 + 2) * GC + dc * 4]);
                const float4 x3 = *reinterpret_cast<const float4*>(&s->xin[(j0 + 3) * GC + dc * 4]);
                const float w0 = wreg[dc * 4], w1 = wreg[dc * 4 + 1];
                const float w2 = wreg[dc * 4 + 2], w3 = wreg[dc * 4 + 3];
                a0 += x0.x * w0 + x0.y * w1 + x0.z * w2 + x0.w * w3;
                a1 += x1.x * w0 + x1.y * w1 + x1.z * w2 + x1.w * w3;
                a2 += x2.x * w0 + x2.y * w1 + x2.z * w2 + x2.w * w3;
                a3 += x3.x * w0 + x3.y * w1 + x3.z * w2 + x3.w * w3;
            }
            s->xl[h * SH + (j0 + 0) * SJ + f] = a0;
            s->xl[h * SH + (j0 + 1) * SJ + f] = a1;
            s->xl[h * SH + (j0 + 2) * SJ + f] = a2;
            s->xl[h * SH + (j0 + 3) * SJ + f] = a3;
        }
    }
    __syncthreads();

    if (tid < 256) {
        int j = tid >> 2, h = tid & 3;
        const float4* xp4 = reinterpret_cast<const float4*>(&s->xl[h * SH + j * SJ]);
        const float4* as4 = reinterpret_cast<const float4*>(&s->as[h * GC]);
        const float4* ad4 = reinterpret_cast<const float4*>(&s->ad[h * GC]);
        float sa = 0.f, da = 0.f;
        #pragma unroll
        for (int m = 0; m < 8; m++) {
            float4 xv = xp4[m], av = as4[m], dvv = ad4[m];
            sa += xv.x * av.x + xv.y * av.y + xv.z * av.z + xv.w * av.w;
            da += xv.x * dvv.x + xv.y * dvv.y + xv.z * dvv.z + xv.w * dvv.w;
        }
        s->sv[j * HH + h] = sa;
        s->dv[j * HH + h] = da;
    }
    __syncthreads();

    const int r = tid & 255;
    const int half = tid >> 8;
    const int i = r >> 2, h = r & 3;
    const float di = s->dv[i * HH + h];
    const int deg = s->sdeg[i];
    const float2* erow = &s->earr[i * EST];

    float mx = -1e30f;
    for (int k = 0; k < deg; k++) {
        float2 e = erow[k];
        int j = __float_as_int(e.x);
        float l = di + s->sv[j * HH + h];
        l = l > 0.f ? l : 0.2f * l;
        l += e.y;
        mx = fmaxf(mx, l);
    }
    float acc[GC];
    #pragma unroll
    for (int f = 0; f < GC; f++) acc[f] = 0.f;
    float ssum = 0.f;
    for (int k = half; k < deg; k += 2) {
        float2 e = erow[k];
        int j = __float_as_int(e.x);
        float l = di + s->sv[j * HH + h];
        l = l > 0.f ? l : 0.2f * l;
        l += e.y;
        float w = __expf(l - mx);
        ssum += w;
        const float4* xp4 = reinterpret_cast<const float4*>(&s->xl[h * SH + j * SJ]);
        #pragma unroll
        for (int m = 0; m < 8; m++) {
            float4 v = xp4[m];
            acc[m * 4 + 0] += w * v.x; acc[m * 4 + 1] += w * v.y;
            acc[m * 4 + 2] += w * v.z; acc[m * 4 + 3] += w * v.w;
        }
    }
    if (half == 1) {
        #pragma unroll
        for (int f = 0; f < GC; f++) s->abuf[r * 33 + f] = acc[f];
        s->sbuf[r] = ssum;
    }
    __syncthreads();
    if (half == 0) {
        ssum += s->sbuf[r];
        #pragma unroll
        for (int f = 0; f < GC; f++) acc[f] += s->abuf[r * 33 + f];
        const float inv = 1.f / ssum;
        #pragma unroll
        for (int f = 0; f < GC; f++) {
            float v = acc[f] * inv;
            v += __shfl_xor_sync(0xffffffffu, v, 1);
            v += __shfl_xor_sync(0xffffffffu, v, 2);
            acc[f] = v * 0.25f;
        }
        if (h == 0) {
            float vals[GC];
            #pragma unroll
            for (int f = 0; f < GC; f++) {
                float o = acc[f] + s->bias[f];
                o = o * s->bns[f] + s->bnb[f];
                vals[f] = geluf(o + s->xin[i * GC + f]);
            }
            #pragma unroll
            for (int f = 0; f < GC; f++) {
                float v = vals[f];
                v += __shfl_xor_sync(0x11111111u, v, 4);
                v += __shfl_xor_sync(0x11111111u, v, 8);
                v += __shfl_xor_sync(0x11111111u, v, 16);
                if ((tid & 31) == 0) atomicAdd(&s->bsum[f], v);
            }
        }
    }
    __syncthreads();
    if (tid < GC) {
        atomicAdd(&g_sum2[tid], s->bsum[tid]);
        g_pooled[b * GC + tid] = s->bsum[tid] * (1.f / (float)CC);
    }
}

// ---------------------------------------------------------------------------
// Final: SE2 gate + classifier
// ---------------------------------------------------------------------------
__global__ __launch_bounds__(256) void final_kernel(
    const float* __restrict__ se2w1, const float* __restrict__ se2w2,
    const float* __restrict__ clfw, const float* __restrict__ clfb,
    float* __restrict__ out)
{
    __shared__ float hid[8];
    __shared__ float gate[GC];
    const int tid = threadIdx.x;
    if (tid < 8) {
        float a = 0.f;
        #pragma unroll
        for (int f = 0; f < GC; f++) a += (g_sum2[f] * (1.f / (float)NSIG)) * se2w1[tid * GC + f];
        hid[tid] = a > 0.f ? a : 0.f;
    }
    __syncthreads();
    if (tid < GC) {
        float a = 0.f;
        #pragma unroll
        for (int k = 0; k < 8; k++) a += hid[k] * se2w2[tid * 8 + k];
        gate[tid] = 1.f / (1.f + __expf(-a));
    }
    __syncthreads();
    {
        int b = tid >> 1, n = tid & 1;
        float a = clfb[n];
        #pragma unroll
        for (int f = 0; f < GC; f++)
            a += g_pooled[b * GC + f] * gate[f] * clfw[n * GC + f];
        out[b * NCLS + n] = a;
    }
}

// ---------------------------------------------------------------------------
// kernel_launch
// ---------------------------------------------------------------------------
extern "C" void kernel_launch(void* const* d_in, const int* in_sizes, int n_in,
                              void* d_out, int out_size)
{
    const float* x         = (const float*)d_in[0];
    const int*   edges     = (const int*)  d_in[1];
    const float* conv1_w   = (const float*)d_in[2];
    const float* bn_c1     = (const float*)d_in[3];
    const float* dw_w      = (const float*)d_in[4];
    const float* bn_c2     = (const float*)d_in[5];
    const float* sdw_w     = (const float*)d_in[6];
    const float* spw_w     = (const float*)d_in[7];
    const float* bn_c3     = (const float*)d_in[8];
    const float* node_emb  = (const float*)d_in[9];
    const float* gat1_w    = (const float*)d_in[10];
    const float* gat1_as   = (const float*)d_in[11];
    const float* gat1_ad   = (const float*)d_in[12];
    const float* gat1_b    = (const float*)d_in[13];
    const float* bn_g1     = (const float*)d_in[14];
    const float* skip1_w   = (const float*)d_in[15];
    const float* se1_w1    = (const float*)d_in[16];
    const float* se1_w2    = (const float*)d_in[17];
    const float* gat2_w    = (const float*)d_in[18];
    const float* gat2_as   = (const float*)d_in[19];
    const float* gat2_ad   = (const float*)d_in[20];
    const float* gat2_b    = (const float*)d_in[21];
    const float* bn_g2     = (const float*)d_in[22];
    const float* se2_w1    = (const float*)d_in[23];
    const float* se2_w2    = (const float*)d_in[24];
    const float* clf_w     = (const float*)d_in[25];
    const float* clf_b     = (const float*)d_in[26];
    float* out = (float*)d_out;

    cudaFuncSetAttribute(extractor_kernel, cudaFuncAttributeMaxDynamicSharedMemorySize, (int)sizeof(ExSmem));
    cudaFuncSetAttribute(gat1_kernel,      cudaFuncAttributeMaxDynamicSharedMemorySize, (int)sizeof(G1Smem));
    cudaFuncSetAttribute(gat2_kernel,      cudaFuncAttributeMaxDynamicSharedMemorySize, (int)sizeof(G2Smem));

    extractor_kernel<<<NSIG + 1, 256, sizeof(ExSmem)>>>(x, conv1_w, bn_c1, dw_w, bn_c2,
                                                        sdw_w, spw_w, bn_c3,
                                                        gat1_w, gat1_as, gat1_ad, skip1_w,
                                                        node_emb, edges);
    gat1_kernel<<<BB, 512, sizeof(G1Smem)>>>(gat1_b, bn_g1);
    gat2_kernel<<<BB, 512, sizeof(G2Smem)>>>(gat2_w, gat2_as, gat2_ad, gat2_b, bn_g2, se1_w1, se1_w2);
    final_kernel<<<1, 256>>>(se2_w1, se2_w2, clf_w, clf_b, out);
}